// round 1
// baseline (speedup 1.0000x reference)
#include <cuda_runtime.h>

// ---------------------------------------------------------------------------
// GraphSAGE with sampling, GB300 baseline (fp32 register-tiled SGEMMs)
//
// Pipeline:
//   k_h0      : h0 = node_emb[parent0+1] + leaky(content0 @ Wp.T + bp)   [S0,128]
//   k_conv<0> : h1 = normalize(leaky(X@W0.T+b0) + leaky(agg@Wagg0.T+bagg0))
//               where agg[i] = mean of 8 random neighbors (self-edge cancels)
//   k_conv<1> : out = (X@W1.T+b1) + (agg@Wagg1.T+bagg1)  (no leaky, no norm)
//               where agg[i] = (h1[i] + sum8 h1[src] - h0[i]) / 8
// ---------------------------------------------------------------------------

#define FEATC 128
#define CONTC 256
#define S2C   8192
#define S1C   73728        /* S2*9 */
#define S0C   663552       /* S1*9 */

__device__ float g_h0[(long long)S0C * FEATC];   // 339.7 MB scratch
__device__ float g_h1[(long long)S1C * FEATC];   // 37.7 MB scratch

static __device__ __forceinline__ float leaky01(float x) {
    return x < 0.0f ? 0.1f * x : x;
}

// ---------------------------------------------------------------------------
// Kernel A: h0 GEMM.  BM=BN=128, BK=32, 256 threads, 8x8 register tile with
// 4+4 split rows/cols (classic conflict-free SIMT layout).
// ---------------------------------------------------------------------------
__global__ __launch_bounds__(256) void k_h0(
    const float* __restrict__ content,   // [S0,256]
    const float* __restrict__ Wp,        // [128,256]
    const float* __restrict__ bp,        // [128]
    const float* __restrict__ node_emb,  // [N+1,128]
    const int*   __restrict__ parent)    // [S0]
{
    __shared__ float As[32][132];
    __shared__ float Bs[32][132];

    const int tid = threadIdx.x;
    const int tx = tid & 15;        // 16 col-groups
    const int ty = tid >> 4;        // 16 row-groups
    const long long m0 = (long long)blockIdx.x * 128;

    float acc[8][8];
#pragma unroll
    for (int i = 0; i < 8; i++)
#pragma unroll
        for (int j = 0; j < 8; j++) acc[i][j] = 0.0f;

    for (int k0 = 0; k0 < CONTC; k0 += 32) {
        // cooperative load: 128x32 of A (transposed into smem) and of Wp
#pragma unroll
        for (int it = 0; it < 4; ++it) {
            int id = tid + 256 * it;          // 0..1023
            int r  = id >> 3;                 // 0..127
            int c  = (id & 7) << 2;           // 0,4,...,28
            float4 v = *(const float4*)(content + (m0 + r) * (long long)CONTC + k0 + c);
            As[c + 0][r] = v.x; As[c + 1][r] = v.y; As[c + 2][r] = v.z; As[c + 3][r] = v.w;
            float4 w = *(const float4*)(Wp + (long long)r * CONTC + k0 + c);
            Bs[c + 0][r] = w.x; Bs[c + 1][r] = w.y; Bs[c + 2][r] = w.z; Bs[c + 3][r] = w.w;
        }
        __syncthreads();

#pragma unroll
        for (int kk = 0; kk < 32; kk++) {
            float a[8], b[8];
            *(float4*)&a[0] = *(const float4*)&As[kk][ty * 4];
            *(float4*)&a[4] = *(const float4*)&As[kk][64 + ty * 4];
            *(float4*)&b[0] = *(const float4*)&Bs[kk][tx * 4];
            *(float4*)&b[4] = *(const float4*)&Bs[kk][64 + tx * 4];
#pragma unroll
            for (int i = 0; i < 8; i++)
#pragma unroll
                for (int j = 0; j < 8; j++)
                    acc[i][j] = fmaf(a[i], b[j], acc[i][j]);
        }
        __syncthreads();
    }

    // epilogue: bias + leaky + node_emb gather, store h0
#pragma unroll
    for (int i = 0; i < 8; i++) {
        int rl = (i < 4) ? (ty * 4 + i) : (64 + ty * 4 + i - 4);
        long long r = m0 + rl;
        long long p = (long long)parent[r] + 1;
        const float* ne = node_emb + p * FEATC;
#pragma unroll
        for (int jh = 0; jh < 2; jh++) {
            int c = (jh ? 64 : 0) + tx * 4;
            float4 bv = *(const float4*)(bp + c);
            float4 nv = *(const float4*)(ne + c);
            float4 o;
            o.x = leaky01(acc[i][jh * 4 + 0] + bv.x) + nv.x;
            o.y = leaky01(acc[i][jh * 4 + 1] + bv.y) + nv.y;
            o.z = leaky01(acc[i][jh * 4 + 2] + bv.z) + nv.z;
            o.w = leaky01(acc[i][jh * 4 + 3] + bv.w) + nv.w;
            *(float4*)(g_h0 + r * FEATC + c) = o;
        }
    }
}

// ---------------------------------------------------------------------------
// Conv kernel (both layers). Per block: 128 dst rows.
//  phase 1: build h_agg tile in smem (gather-mean of 8 neighbors)
//  phase 2: acc1 = [h_dst | h_agg] @ W.T  (K=256)
//           acc2 = h_agg @ Wagg.T         (K=128, fused into k0>=128 steps)
//  phase 3: epilogue (leaky + rownorm for layer 0; plain sum for layer 1)
// ---------------------------------------------------------------------------
#define CONV_SMEM_FLOATS (128 * 128 + 3 * 32 * 132)

template <int LAYER>
__global__ __launch_bounds__(256) void k_conv(
    const float* __restrict__ W,     // [128,256]
    const float* __restrict__ b,     // [128]
    const float* __restrict__ Wagg,  // [128,128]
    const float* __restrict__ bagg,  // [128]
    const int*   __restrict__ nbr,   // random-edge srcs, nbr[8*dst + k]
    float*       __restrict__ dout)  // layer1 output (unused for layer0)
{
    extern __shared__ float sm[];
    float (*Sagg)[128] = (float(*)[128])sm;                       // 64 KB
    float* xs_base = sm + 128 * 128;
    float (*Xs)[132]  = (float(*)[132])xs_base;                    // 16.9 KB
    float (*Bs)[132]  = (float(*)[132])(xs_base + 32 * 132);
    float (*Bs2)[132] = (float(*)[132])(xs_base + 2 * 32 * 132);

    const int tid  = threadIdx.x;
    const int lane = tid & 31, warp = tid >> 5;
    const int tx = tid & 15, ty = tid >> 4;
    const long long m0 = (long long)blockIdx.x * 128;
    const float* hsrc = (LAYER == 0) ? g_h0 : g_h1;
    float* outp = (LAYER == 0) ? g_h1 : dout;

    // ---- phase 1: aggregate neighbors into Sagg ----
    for (int rr = warp; rr < 128; rr += 8) {
        long long drow = m0 + rr;
        const int* e = nbr + drow * 8;
        float4 s = make_float4(0.f, 0.f, 0.f, 0.f);
#pragma unroll
        for (int k = 0; k < 8; k++) {
            long long si = e[k];
            float4 v = *(const float4*)(hsrc + si * FEATC + lane * 4);
            s.x += v.x; s.y += v.y; s.z += v.z; s.w += v.w;
        }
        if (LAYER == 1) {
            // self-edge contributes h1[drow], h_dst is h0[drow]
            float4 v1 = *(const float4*)(g_h1 + drow * FEATC + lane * 4);
            float4 v0 = *(const float4*)(g_h0 + drow * FEATC + lane * 4);
            s.x += v1.x - v0.x; s.y += v1.y - v0.y;
            s.z += v1.z - v0.z; s.w += v1.w - v0.w;
        }
        s.x *= 0.125f; s.y *= 0.125f; s.z *= 0.125f; s.w *= 0.125f;
        *(float4*)&Sagg[rr][lane * 4] = s;
    }
    __syncthreads();

    // ---- phase 2: GEMMs ----
    float acc1[8][8], acc2[8][8];
#pragma unroll
    for (int i = 0; i < 8; i++)
#pragma unroll
        for (int j = 0; j < 8; j++) { acc1[i][j] = 0.0f; acc2[i][j] = 0.0f; }

    for (int k0 = 0; k0 < 256; k0 += 32) {
        const bool second = (k0 >= 128);
        if (!second) {
            // X[:, k0..k0+31] = h_dst columns, from g_h0 rows m0..m0+127
#pragma unroll
            for (int it = 0; it < 4; ++it) {
                int id = tid + 256 * it;
                int r = id >> 3, c = (id & 7) << 2;
                float4 v = *(const float4*)(g_h0 + (m0 + r) * (long long)FEATC + k0 + c);
                Xs[c + 0][r] = v.x; Xs[c + 1][r] = v.y; Xs[c + 2][r] = v.z; Xs[c + 3][r] = v.w;
            }
        }
#pragma unroll
        for (int it = 0; it < 4; ++it) {
            int id = tid + 256 * it;
            int n = id >> 3, c = (id & 7) << 2;
            float4 w = *(const float4*)(W + (long long)n * 256 + k0 + c);
            Bs[c + 0][n] = w.x; Bs[c + 1][n] = w.y; Bs[c + 2][n] = w.z; Bs[c + 3][n] = w.w;
        }
        if (second) {
#pragma unroll
            for (int it = 0; it < 4; ++it) {
                int id = tid + 256 * it;
                int n = id >> 3, c = (id & 7) << 2;
                float4 w = *(const float4*)(Wagg + (long long)n * 128 + (k0 - 128) + c);
                Bs2[c + 0][n] = w.x; Bs2[c + 1][n] = w.y; Bs2[c + 2][n] = w.z; Bs2[c + 3][n] = w.w;
            }
        }
        __syncthreads();

        if (!second) {
#pragma unroll
            for (int kk = 0; kk < 32; kk++) {
                float a[8], bb[8];
                *(float4*)&a[0] = *(const float4*)&Xs[kk][ty * 4];
                *(float4*)&a[4] = *(const float4*)&Xs[kk][64 + ty * 4];
                *(float4*)&bb[0] = *(const float4*)&Bs[kk][tx * 4];
                *(float4*)&bb[4] = *(const float4*)&Bs[kk][64 + tx * 4];
#pragma unroll
                for (int i = 0; i < 8; i++)
#pragma unroll
                    for (int j = 0; j < 8; j++)
                        acc1[i][j] = fmaf(a[i], bb[j], acc1[i][j]);
            }
        } else {
#pragma unroll
            for (int kk = 0; kk < 32; kk++) {
                int kc = k0 - 128 + kk;
                float a[8], bb[8], bb2[8];
#pragma unroll
                for (int i = 0; i < 8; i++) {
                    int rl = (i < 4) ? (ty * 4 + i) : (64 + ty * 4 + i - 4);
                    a[i] = Sagg[rl][kc];
                }
                *(float4*)&bb[0]  = *(const float4*)&Bs[kk][tx * 4];
                *(float4*)&bb[4]  = *(const float4*)&Bs[kk][64 + tx * 4];
                *(float4*)&bb2[0] = *(const float4*)&Bs2[kk][tx * 4];
                *(float4*)&bb2[4] = *(const float4*)&Bs2[kk][64 + tx * 4];
#pragma unroll
                for (int i = 0; i < 8; i++)
#pragma unroll
                    for (int j = 0; j < 8; j++) {
                        acc1[i][j] = fmaf(a[i], bb[j],  acc1[i][j]);
                        acc2[i][j] = fmaf(a[i], bb2[j], acc2[i][j]);
                    }
            }
        }
        __syncthreads();
    }

    // ---- phase 3: epilogue; result written in-place into acc1 ----
#pragma unroll
    for (int jh = 0; jh < 2; jh++) {
        int c = (jh ? 64 : 0) + tx * 4;
        float4 bv = *(const float4*)(b + c);
        float4 gv = *(const float4*)(bagg + c);
#pragma unroll
        for (int i = 0; i < 8; i++) {
#pragma unroll
            for (int j2 = 0; j2 < 4; j2++) {
                float t1 = acc1[i][jh * 4 + j2] + ((const float*)&bv)[j2];
                float t2 = acc2[i][jh * 4 + j2] + ((const float*)&gv)[j2];
                if (LAYER == 0) { t1 = leaky01(t1); t2 = leaky01(t2); }
                acc1[i][jh * 4 + j2] = t1 + t2;
            }
        }
    }

    if (LAYER == 0) {
        // row-wise L2 normalization
        float (*red)[16] = (float(*)[16])xs_base;       // overlays Xs (safe: synced)
        float* scales = xs_base + 128 * 16;
#pragma unroll
        for (int i = 0; i < 8; i++) {
            int rl = (i < 4) ? (ty * 4 + i) : (64 + ty * 4 + i - 4);
            float p = 0.f;
#pragma unroll
            for (int j = 0; j < 8; j++) p = fmaf(acc1[i][j], acc1[i][j], p);
            red[rl][tx] = p;
        }
        __syncthreads();
        if (tid < 128) {
            float s = 0.f;
#pragma unroll
            for (int t = 0; t < 16; t++) s += red[tid][t];
            scales[tid] = 1.0f / fmaxf(sqrtf(s), 1e-6f);
        }
        __syncthreads();
#pragma unroll
        for (int i = 0; i < 8; i++) {
            int rl = (i < 4) ? (ty * 4 + i) : (64 + ty * 4 + i - 4);
            float sc = scales[rl];
#pragma unroll
            for (int jh = 0; jh < 2; jh++) {
                int c = (jh ? 64 : 0) + tx * 4;
                float4 o;
                o.x = acc1[i][jh * 4 + 0] * sc;
                o.y = acc1[i][jh * 4 + 1] * sc;
                o.z = acc1[i][jh * 4 + 2] * sc;
                o.w = acc1[i][jh * 4 + 3] * sc;
                *(float4*)(outp + (m0 + rl) * (long long)FEATC + c) = o;
            }
        }
    } else {
#pragma unroll
        for (int i = 0; i < 8; i++) {
            int rl = (i < 4) ? (ty * 4 + i) : (64 + ty * 4 + i - 4);
#pragma unroll
            for (int jh = 0; jh < 2; jh++) {
                int c = (jh ? 64 : 0) + tx * 4;
                float4 o;
                o.x = acc1[i][jh * 4 + 0];
                o.y = acc1[i][jh * 4 + 1];
                o.z = acc1[i][jh * 4 + 2];
                o.w = acc1[i][jh * 4 + 3];
                *(float4*)(outp + (m0 + rl) * (long long)FEATC + c) = o;
            }
        }
    }
}

// ---------------------------------------------------------------------------
// kernel_launch
// ---------------------------------------------------------------------------
extern "C" void kernel_launch(void* const* d_in, const int* in_sizes, int n_in,
                              void* d_out, int out_size)
{
    const float* node_emb = (const float*)d_in[0];
    const float* content0 = (const float*)d_in[1];
    const float* Wp    = (const float*)d_in[2];
    const float* bp    = (const float*)d_in[3];
    const float* W0    = (const float*)d_in[4];
    const float* b0    = (const float*)d_in[5];
    const float* Wagg0 = (const float*)d_in[6];
    const float* bagg0 = (const float*)d_in[7];
    const float* W1    = (const float*)d_in[8];
    const float* b1    = (const float*)d_in[9];
    const float* Wagg1 = (const float*)d_in[10];
    const float* bagg1 = (const float*)d_in[11];
    const int* parent0 = (const int*)d_in[12];
    const int* src0    = (const int*)d_in[13];
    // d_in[14] = dst0 (structure known, unused)
    const int* src1    = (const int*)d_in[15];
    // d_in[16] = dst1 (unused)
    float* out = (float*)d_out;

    const int smem_conv = CONV_SMEM_FLOATS * (int)sizeof(float);  // 116224 B
    cudaFuncSetAttribute(k_conv<0>, cudaFuncAttributeMaxDynamicSharedMemorySize, smem_conv);
    cudaFuncSetAttribute(k_conv<1>, cudaFuncAttributeMaxDynamicSharedMemorySize, smem_conv);

    k_h0<<<S0C / 128, 256>>>(content0, Wp, bp, node_emb, parent0);
    // random edges start after the S1 (resp. S2) self-edges in src arrays
    k_conv<0><<<S1C / 128, 256, smem_conv>>>(W0, b0, Wagg0, bagg0, src0 + S1C, nullptr);
    k_conv<1><<<S2C / 128, 256, smem_conv>>>(W1, b1, Wagg1, bagg1, src1 + S2C, out);
}

// round 3
// speedup vs baseline: 1.4803x; 1.4803x over previous
#include <cuda_runtime.h>
#include <cuda_bf16.h>
#include <cstdint>

// ---------------------------------------------------------------------------
// GraphSAGE with sampling, GB300.
// NOTE: harness builds via compute_103 virtual arch -> tcgen05 unavailable.
// Tensor path uses classic mma.sync bf16 (HMMA) with 3-term hi/lo split.
//
//  k_prep    : split Wp into bf16 hi/lo globals
//  k_h0_mma  : h0 = node_emb[parent0+1] + leaky(content0 @ Wp.T + bp)
//  k_conv<0> : h1 = normalize(leaky(X@W0.T+b0) + leaky(agg@Wagg0.T+bagg0))
//  k_conv<1> : out = (X@W1.T+b1) + (agg@Wagg1.T+bagg1)
// ---------------------------------------------------------------------------

#define FEATC 128
#define CONTC 256
#define S2C   8192
#define S1C   73728        /* S2*9 */
#define S0C   663552       /* S1*9 */

__device__ float g_h0[(long long)S0C * FEATC];   // 339.7 MB scratch
__device__ float g_h1[(long long)S1C * FEATC];   // 37.7 MB scratch
__device__ __nv_bfloat16 g_wp_hi[FEATC * CONTC];
__device__ __nv_bfloat16 g_wp_lo[FEATC * CONTC];

static __device__ __forceinline__ float leaky01(float x) {
    return x < 0.0f ? 0.1f * x : x;
}
static __device__ __forceinline__ uint32_t b2u(__nv_bfloat162 h) {
    return *reinterpret_cast<uint32_t*>(&h);
}

// mma.sync m16n8k16 row.col f32.bf16.bf16.f32, accumulate in place
static __device__ __forceinline__ void mma16816(
    float* c, const uint32_t* a, const uint32_t* b)
{
    asm volatile(
        "mma.sync.aligned.m16n8k16.row.col.f32.bf16.bf16.f32 "
        "{%0,%1,%2,%3}, {%4,%5,%6,%7}, {%8,%9}, {%0,%1,%2,%3};"
        : "+f"(c[0]), "+f"(c[1]), "+f"(c[2]), "+f"(c[3])
        : "r"(a[0]), "r"(a[1]), "r"(a[2]), "r"(a[3]),
          "r"(b[0]), "r"(b[1]));
}

// ---------------------------------------------------------------------------
// k_prep: split Wp into bf16 hi/lo.  32768 elements.
// ---------------------------------------------------------------------------
__global__ void k_prep(const float* __restrict__ Wp)
{
    int i = blockIdx.x * blockDim.x + threadIdx.x;
    if (i < FEATC * CONTC) {
        float v = Wp[i];
        __nv_bfloat16 h = __float2bfloat16_rn(v);
        g_wp_hi[i] = h;
        g_wp_lo[i] = __float2bfloat16_rn(v - __bfloat162float(h));
    }
}

// ---------------------------------------------------------------------------
// k_h0_mma: 128x128 CTA tile, K=256 in chunks of 64.
// 8 warps: warp (w&3) -> m-block of 32 rows, (w>>2) -> n-block of 64 cols.
// A (content) loaded global->registers, split to bf16 hi/lo in-flight.
// B (Wp hi/lo) staged per-chunk in smem, rows padded to 72 bf16 (conflict-free).
// ---------------------------------------------------------------------------
#define BPAD 72

__global__ __launch_bounds__(256, 2) void k_h0_mma(
    const float* __restrict__ content,   // [S0,256]
    const float* __restrict__ bp,        // [128]
    const float* __restrict__ node_emb,  // [N+1,128]
    const int*   __restrict__ parent)    // [S0]
{
    __shared__ __nv_bfloat16 Bh[128 * BPAD];
    __shared__ __nv_bfloat16 Bl[128 * BPAD];

    const int tid  = threadIdx.x;
    const int lane = tid & 31;
    const int warp = tid >> 5;
    const int wm   = warp & 3;          // m block (0..3) * 32 rows
    const int wn   = warp >> 2;         // n block (0..1) * 64 cols
    const int gID  = lane >> 2;         // 0..7
    const int qid  = lane & 3;          // 0..3
    const long long m0 = (long long)blockIdx.x * 128;
    const int mbase = wm * 32;
    const int nbase = wn * 64;

    float acc[2][8][4];
#pragma unroll
    for (int mi = 0; mi < 2; mi++)
#pragma unroll
        for (int nj = 0; nj < 8; nj++)
#pragma unroll
            for (int t = 0; t < 4; t++) acc[mi][nj][t] = 0.0f;

    for (int kc = 0; kc < 4; kc++) {
        // ---- stage B chunk [128 n][64 k] hi+lo into smem ----
#pragma unroll
        for (int it = 0; it < 4; it++) {
            int g = tid + 256 * it;       // 0..1023 uint4 groups
            int n = g >> 3;               // 0..127
            int c = (g & 7) * 8;          // 0..56
            *(uint4*)&Bh[n * BPAD + c] = *(const uint4*)(g_wp_hi + n * CONTC + kc * 64 + c);
            *(uint4*)&Bl[n * BPAD + c] = *(const uint4*)(g_wp_lo + n * CONTC + kc * 64 + c);
        }
        __syncthreads();

#pragma unroll
        for (int s = 0; s < 4; s++) {     // k16 steps within chunk
            // ---- A fragments: global load + hi/lo split ----
            uint32_t ah[2][4], al[2][4];
            const float* abase = content + (m0 + mbase + gID) * (long long)CONTC
                               + kc * 64 + s * 16 + qid * 2;
#pragma unroll
            for (int mi = 0; mi < 2; mi++) {
#pragma unroll
                for (int rr = 0; rr < 2; rr++) {          // row gID / gID+8
#pragma unroll
                    for (int kk = 0; kk < 2; kk++) {      // k +0 / +8
                        float2 v = *(const float2*)(abase + (mi * 16 + rr * 8) * CONTC + kk * 8);
                        __nv_bfloat162 h = __floats2bfloat162_rn(v.x, v.y);
                        float rx = v.x - __bfloat162float(h.x);
                        float ry = v.y - __bfloat162float(h.y);
                        __nv_bfloat162 l = __floats2bfloat162_rn(rx, ry);
                        ah[mi][rr + kk * 2] = b2u(h);     // reg order: a0a1,a2a3,a4a5,a6a7
                        al[mi][rr + kk * 2] = b2u(l);
                    }
                }
            }
            // ---- B fragments + MMAs ----
#pragma unroll
            for (int nj = 0; nj < 8; nj++) {
                int n  = nbase + nj * 8 + gID;
                int cb = s * 16 + qid * 2;
                uint32_t bh[2], bl[2];
                bh[0] = *(const uint32_t*)&Bh[n * BPAD + cb];
                bh[1] = *(const uint32_t*)&Bh[n * BPAD + cb + 8];
                bl[0] = *(const uint32_t*)&Bl[n * BPAD + cb];
                bl[1] = *(const uint32_t*)&Bl[n * BPAD + cb + 8];
                mma16816(acc[0][nj], ah[0], bh);
                mma16816(acc[1][nj], ah[1], bh);
                mma16816(acc[0][nj], al[0], bh);
                mma16816(acc[1][nj], al[1], bh);
                mma16816(acc[0][nj], ah[0], bl);
                mma16816(acc[1][nj], ah[1], bl);
            }
        }
        __syncthreads();
    }

    // ---- epilogue: bias + leaky + node_emb gather -> g_h0 ----
#pragma unroll
    for (int mi = 0; mi < 2; mi++) {
#pragma unroll
        for (int rr = 0; rr < 2; rr++) {
            long long r = m0 + mbase + mi * 16 + rr * 8 + gID;
            long long p = (long long)parent[r] + 1;
            const float* ne = node_emb + p * FEATC;
            float* orow = g_h0 + r * FEATC;
#pragma unroll
            for (int nj = 0; nj < 8; nj++) {
                int c = nbase + nj * 8 + qid * 2;
                float2 bv = *(const float2*)(bp + c);
                float2 nv = *(const float2*)(ne + c);
                float2 o;
                o.x = leaky01(acc[mi][nj][rr * 2 + 0] + bv.x) + nv.x;
                o.y = leaky01(acc[mi][nj][rr * 2 + 1] + bv.y) + nv.y;
                *(float2*)(orow + c) = o;
            }
        }
    }
}

// ---------------------------------------------------------------------------
// Conv kernel (both layers) — unchanged from round 1 (passing version).
// ---------------------------------------------------------------------------
#define CONV_SMEM_FLOATS (128 * 128 + 3 * 32 * 132)

template <int LAYER>
__global__ __launch_bounds__(256) void k_conv(
    const float* __restrict__ W,     // [128,256]
    const float* __restrict__ b,     // [128]
    const float* __restrict__ Wagg,  // [128,128]
    const float* __restrict__ bagg,  // [128]
    const int*   __restrict__ nbr,   // random-edge srcs, nbr[8*dst + k]
    float*       __restrict__ dout)
{
    extern __shared__ float sm[];
    float (*Sagg)[128] = (float(*)[128])sm;
    float* xs_base = sm + 128 * 128;
    float (*Xs)[132]  = (float(*)[132])xs_base;
    float (*Bs)[132]  = (float(*)[132])(xs_base + 32 * 132);
    float (*Bs2)[132] = (float(*)[132])(xs_base + 2 * 32 * 132);

    const int tid  = threadIdx.x;
    const int lane = tid & 31, warp = tid >> 5;
    const int tx = tid & 15, ty = tid >> 4;
    const long long m0 = (long long)blockIdx.x * 128;
    const float* hsrc = (LAYER == 0) ? g_h0 : g_h1;
    float* outp = (LAYER == 0) ? g_h1 : dout;

    for (int rr = warp; rr < 128; rr += 8) {
        long long drow = m0 + rr;
        const int* e = nbr + drow * 8;
        float4 s = make_float4(0.f, 0.f, 0.f, 0.f);
#pragma unroll
        for (int k = 0; k < 8; k++) {
            long long si = e[k];
            float4 v = *(const float4*)(hsrc + si * FEATC + lane * 4);
            s.x += v.x; s.y += v.y; s.z += v.z; s.w += v.w;
        }
        if (LAYER == 1) {
            float4 v1 = *(const float4*)(g_h1 + drow * FEATC + lane * 4);
            float4 v0 = *(const float4*)(g_h0 + drow * FEATC + lane * 4);
            s.x += v1.x - v0.x; s.y += v1.y - v0.y;
            s.z += v1.z - v0.z; s.w += v1.w - v0.w;
        }
        s.x *= 0.125f; s.y *= 0.125f; s.z *= 0.125f; s.w *= 0.125f;
        *(float4*)&Sagg[rr][lane * 4] = s;
    }
    __syncthreads();

    float acc1[8][8], acc2[8][8];
#pragma unroll
    for (int i = 0; i < 8; i++)
#pragma unroll
        for (int j = 0; j < 8; j++) { acc1[i][j] = 0.0f; acc2[i][j] = 0.0f; }

    for (int k0 = 0; k0 < 256; k0 += 32) {
        const bool second = (k0 >= 128);
        if (!second) {
#pragma unroll
            for (int it = 0; it < 4; ++it) {
                int id = tid + 256 * it;
                int r = id >> 3, c = (id & 7) << 2;
                float4 v = *(const float4*)(g_h0 + (m0 + r) * (long long)FEATC + k0 + c);
                Xs[c + 0][r] = v.x; Xs[c + 1][r] = v.y; Xs[c + 2][r] = v.z; Xs[c + 3][r] = v.w;
            }
        }
#pragma unroll
        for (int it = 0; it < 4; ++it) {
            int id = tid + 256 * it;
            int n = id >> 3, c = (id & 7) << 2;
            float4 w = *(const float4*)(W + (long long)n * 256 + k0 + c);
            Bs[c + 0][n] = w.x; Bs[c + 1][n] = w.y; Bs[c + 2][n] = w.z; Bs[c + 3][n] = w.w;
        }
        if (second) {
#pragma unroll
            for (int it = 0; it < 4; ++it) {
                int id = tid + 256 * it;
                int n = id >> 3, c = (id & 7) << 2;
                float4 w = *(const float4*)(Wagg + (long long)n * 128 + (k0 - 128) + c);
                Bs2[c + 0][n] = w.x; Bs2[c + 1][n] = w.y; Bs2[c + 2][n] = w.z; Bs2[c + 3][n] = w.w;
            }
        }
        __syncthreads();

        if (!second) {
#pragma unroll
            for (int kk = 0; kk < 32; kk++) {
                float a[8], bb[8];
                *(float4*)&a[0] = *(const float4*)&Xs[kk][ty * 4];
                *(float4*)&a[4] = *(const float4*)&Xs[kk][64 + ty * 4];
                *(float4*)&bb[0] = *(const float4*)&Bs[kk][tx * 4];
                *(float4*)&bb[4] = *(const float4*)&Bs[kk][64 + tx * 4];
#pragma unroll
                for (int i = 0; i < 8; i++)
#pragma unroll
                    for (int j = 0; j < 8; j++)
                        acc1[i][j] = fmaf(a[i], bb[j], acc1[i][j]);
            }
        } else {
#pragma unroll
            for (int kk = 0; kk < 32; kk++) {
                int kcc = k0 - 128 + kk;
                float a[8], bb[8], bb2[8];
#pragma unroll
                for (int i = 0; i < 8; i++) {
                    int rl = (i < 4) ? (ty * 4 + i) : (64 + ty * 4 + i - 4);
                    a[i] = Sagg[rl][kcc];
                }
                *(float4*)&bb[0]  = *(const float4*)&Bs[kk][tx * 4];
                *(float4*)&bb[4]  = *(const float4*)&Bs[kk][64 + tx * 4];
                *(float4*)&bb2[0] = *(const float4*)&Bs2[kk][tx * 4];
                *(float4*)&bb2[4] = *(const float4*)&Bs2[kk][64 + tx * 4];
#pragma unroll
                for (int i = 0; i < 8; i++)
#pragma unroll
                    for (int j = 0; j < 8; j++) {
                        acc1[i][j] = fmaf(a[i], bb[j],  acc1[i][j]);
                        acc2[i][j] = fmaf(a[i], bb2[j], acc2[i][j]);
                    }
            }
        }
        __syncthreads();
    }

#pragma unroll
    for (int jh = 0; jh < 2; jh++) {
        int c = (jh ? 64 : 0) + tx * 4;
        float4 bv = *(const float4*)(b + c);
        float4 gv = *(const float4*)(bagg + c);
#pragma unroll
        for (int i = 0; i < 8; i++) {
#pragma unroll
            for (int j2 = 0; j2 < 4; j2++) {
                float t1 = acc1[i][jh * 4 + j2] + ((const float*)&bv)[j2];
                float t2 = acc2[i][jh * 4 + j2] + ((const float*)&gv)[j2];
                if (LAYER == 0) { t1 = leaky01(t1); t2 = leaky01(t2); }
                acc1[i][jh * 4 + j2] = t1 + t2;
            }
        }
    }

    if (LAYER == 0) {
        float (*red)[16] = (float(*)[16])xs_base;
        float* scales = xs_base + 128 * 16;
#pragma unroll
        for (int i = 0; i < 8; i++) {
            int rl = (i < 4) ? (ty * 4 + i) : (64 + ty * 4 + i - 4);
            float p = 0.f;
#pragma unroll
            for (int j = 0; j < 8; j++) p = fmaf(acc1[i][j], acc1[i][j], p);
            red[rl][tx] = p;
        }
        __syncthreads();
        if (tid < 128) {
            float s = 0.f;
#pragma unroll
            for (int t = 0; t < 16; t++) s += red[tid][t];
            scales[tid] = 1.0f / fmaxf(sqrtf(s), 1e-6f);
        }
        __syncthreads();
#pragma unroll
        for (int i = 0; i < 8; i++) {
            int rl = (i < 4) ? (ty * 4 + i) : (64 + ty * 4 + i - 4);
            float sc = scales[rl];
#pragma unroll
            for (int jh = 0; jh < 2; jh++) {
                int c = (jh ? 64 : 0) + tx * 4;
                float4 o;
                o.x = acc1[i][jh * 4 + 0] * sc;
                o.y = acc1[i][jh * 4 + 1] * sc;
                o.z = acc1[i][jh * 4 + 2] * sc;
                o.w = acc1[i][jh * 4 + 3] * sc;
                *(float4*)(outp + (m0 + rl) * (long long)FEATC + c) = o;
            }
        }
    } else {
#pragma unroll
        for (int i = 0; i < 8; i++) {
            int rl = (i < 4) ? (ty * 4 + i) : (64 + ty * 4 + i - 4);
#pragma unroll
            for (int jh = 0; jh < 2; jh++) {
                int c = (jh ? 64 : 0) + tx * 4;
                float4 o;
                o.x = acc1[i][jh * 4 + 0];
                o.y = acc1[i][jh * 4 + 1];
                o.z = acc1[i][jh * 4 + 2];
                o.w = acc1[i][jh * 4 + 3];
                *(float4*)(outp + (m0 + rl) * (long long)FEATC + c) = o;
            }
        }
    }
}

// ---------------------------------------------------------------------------
// kernel_launch
// ---------------------------------------------------------------------------
extern "C" void kernel_launch(void* const* d_in, const int* in_sizes, int n_in,
                              void* d_out, int out_size)
{
    const float* node_emb = (const float*)d_in[0];
    const float* content0 = (const float*)d_in[1];
    const float* Wp    = (const float*)d_in[2];
    const float* bp    = (const float*)d_in[3];
    const float* W0    = (const float*)d_in[4];
    const float* b0    = (const float*)d_in[5];
    const float* Wagg0 = (const float*)d_in[6];
    const float* bagg0 = (const float*)d_in[7];
    const float* W1    = (const float*)d_in[8];
    const float* b1    = (const float*)d_in[9];
    const float* Wagg1 = (const float*)d_in[10];
    const float* bagg1 = (const float*)d_in[11];
    const int* parent0 = (const int*)d_in[12];
    const int* src0    = (const int*)d_in[13];
    const int* src1    = (const int*)d_in[15];
    float* out = (float*)d_out;

    const int smem_conv = CONV_SMEM_FLOATS * (int)sizeof(float);
    cudaFuncSetAttribute(k_conv<0>, cudaFuncAttributeMaxDynamicSharedMemorySize, smem_conv);
    cudaFuncSetAttribute(k_conv<1>, cudaFuncAttributeMaxDynamicSharedMemorySize, smem_conv);

    k_prep<<<(FEATC * CONTC + 255) / 256, 256>>>(Wp);
    k_h0_mma<<<S0C / 128, 256>>>(content0, bp, node_emb, parent0);
    k_conv<0><<<S1C / 128, 256, smem_conv>>>(W0, b0, Wagg0, bagg0, src0 + S1C, nullptr);
    k_conv<1><<<S2C / 128, 256, smem_conv>>>(W1, b1, Wagg1, bagg1, src1 + S2C, out);
}

// round 6
// speedup vs baseline: 1.7545x; 1.1853x over previous
#include <cuda_runtime.h>
#include <cuda_bf16.h>
#include <cstdint>

// ---------------------------------------------------------------------------
// GraphSAGE with sampling, GB300 (compute_103 virtual arch -> no tcgen05;
// tensor work via mma.sync.m16n8k16 bf16 with 3-term hi/lo split).
// Round 6: conv kernels on HMMA with K-chunk=32 so dynamic smem (106,496 B)
// stays below the 116,224 B that is proven to work in this environment.
// ---------------------------------------------------------------------------

#define FEATC 128
#define CONTC 256
#define S2C   8192
#define S1C   73728        /* S2*9 */
#define S0C   663552       /* S1*9 */

// weight hi/lo pool offsets (elements)
#define OFF_WP    0
#define OFF_W0    32768
#define OFF_WAGG0 65536
#define OFF_W1    81920
#define OFF_WAGG1 114688
#define W_TOTAL   131072

__device__ float g_h0[(long long)S0C * FEATC];   // 339.7 MB scratch
__device__ float g_h1[(long long)S1C * FEATC];   // 37.7 MB scratch
__device__ __nv_bfloat16 g_wh[W_TOTAL];
__device__ __nv_bfloat16 g_wl[W_TOTAL];

static __device__ __forceinline__ float leaky01(float x) {
    return x < 0.0f ? 0.1f * x : x;
}
static __device__ __forceinline__ uint32_t b2u(__nv_bfloat162 h) {
    return *reinterpret_cast<uint32_t*>(&h);
}

// mma.sync m16n8k16 row.col f32.bf16.bf16.f32, accumulate in place
static __device__ __forceinline__ void mma16816(
    float* c, const uint32_t* a, const uint32_t* b)
{
    asm volatile(
        "mma.sync.aligned.m16n8k16.row.col.f32.bf16.bf16.f32 "
        "{%0,%1,%2,%3}, {%4,%5,%6,%7}, {%8,%9}, {%0,%1,%2,%3};"
        : "+f"(c[0]), "+f"(c[1]), "+f"(c[2]), "+f"(c[3])
        : "r"(a[0]), "r"(a[1]), "r"(a[2]), "r"(a[3]),
          "r"(b[0]), "r"(b[1]));
}

// split a float2 into bf16x2 hi + bf16x2 lo packed words
static __device__ __forceinline__ void split2(float2 v, uint32_t& hi, uint32_t& lo)
{
    __nv_bfloat162 h = __floats2bfloat162_rn(v.x, v.y);
    float rx = v.x - __bfloat162float(h.x);
    float ry = v.y - __bfloat162float(h.y);
    __nv_bfloat162 l = __floats2bfloat162_rn(rx, ry);
    hi = b2u(h); lo = b2u(l);
}

// ---------------------------------------------------------------------------
// k_prep: split all weights into bf16 hi/lo pool.
// ---------------------------------------------------------------------------
__global__ void k_prep(const float* __restrict__ Wp, const float* __restrict__ W0,
                       const float* __restrict__ Wagg0, const float* __restrict__ W1,
                       const float* __restrict__ Wagg1)
{
    int i = blockIdx.x * blockDim.x + threadIdx.x;
    if (i >= W_TOTAL) return;
    float v;
    if      (i < OFF_W0)    v = Wp[i - OFF_WP];
    else if (i < OFF_WAGG0) v = W0[i - OFF_W0];
    else if (i < OFF_W1)    v = Wagg0[i - OFF_WAGG0];
    else if (i < OFF_WAGG1) v = W1[i - OFF_W1];
    else                    v = Wagg1[i - OFF_WAGG1];
    __nv_bfloat16 h = __float2bfloat16_rn(v);
    g_wh[i] = h;
    g_wl[i] = __float2bfloat16_rn(v - __bfloat162float(h));
}

// ---------------------------------------------------------------------------
// k_h0_mma: 128x128 CTA tile, K=256 in chunks of 64.  (round-3-proven)
// ---------------------------------------------------------------------------
#define BPAD 72

__global__ __launch_bounds__(256, 2) void k_h0_mma(
    const float* __restrict__ content,   // [S0,256]
    const float* __restrict__ bp,        // [128]
    const float* __restrict__ node_emb,  // [N+1,128]
    const int*   __restrict__ parent)    // [S0]
{
    __shared__ __nv_bfloat16 Bh[128 * BPAD];
    __shared__ __nv_bfloat16 Bl[128 * BPAD];

    const int tid  = threadIdx.x;
    const int lane = tid & 31;
    const int warp = tid >> 5;
    const int wm   = warp & 3;
    const int wn   = warp >> 2;
    const int gID  = lane >> 2;
    const int qid  = lane & 3;
    const long long m0 = (long long)blockIdx.x * 128;
    const int mbase = wm * 32;
    const int nbase = wn * 64;

    float acc[2][8][4];
#pragma unroll
    for (int mi = 0; mi < 2; mi++)
#pragma unroll
        for (int nj = 0; nj < 8; nj++)
#pragma unroll
            for (int t = 0; t < 4; t++) acc[mi][nj][t] = 0.0f;

    for (int kc = 0; kc < 4; kc++) {
#pragma unroll
        for (int it = 0; it < 4; it++) {
            int g = tid + 256 * it;
            int n = g >> 3;
            int c = (g & 7) * 8;
            *(uint4*)&Bh[n * BPAD + c] = *(const uint4*)(g_wh + OFF_WP + n * CONTC + kc * 64 + c);
            *(uint4*)&Bl[n * BPAD + c] = *(const uint4*)(g_wl + OFF_WP + n * CONTC + kc * 64 + c);
        }
        __syncthreads();

#pragma unroll
        for (int s = 0; s < 4; s++) {
            uint32_t ah[2][4], al[2][4];
            const float* abase = content + (m0 + mbase + gID) * (long long)CONTC
                               + kc * 64 + s * 16 + qid * 2;
#pragma unroll
            for (int mi = 0; mi < 2; mi++)
#pragma unroll
                for (int rr = 0; rr < 2; rr++)
#pragma unroll
                    for (int kk = 0; kk < 2; kk++) {
                        float2 v = *(const float2*)(abase + (mi * 16 + rr * 8) * CONTC + kk * 8);
                        split2(v, ah[mi][rr + kk * 2], al[mi][rr + kk * 2]);
                    }
#pragma unroll
            for (int nj = 0; nj < 8; nj++) {
                int n  = nbase + nj * 8 + gID;
                int cb = s * 16 + qid * 2;
                uint32_t bh[2], bl[2];
                bh[0] = *(const uint32_t*)&Bh[n * BPAD + cb];
                bh[1] = *(const uint32_t*)&Bh[n * BPAD + cb + 8];
                bl[0] = *(const uint32_t*)&Bl[n * BPAD + cb];
                bl[1] = *(const uint32_t*)&Bl[n * BPAD + cb + 8];
                mma16816(acc[0][nj], ah[0], bh);
                mma16816(acc[1][nj], ah[1], bh);
                mma16816(acc[0][nj], al[0], bh);
                mma16816(acc[1][nj], al[1], bh);
                mma16816(acc[0][nj], ah[0], bl);
                mma16816(acc[1][nj], ah[1], bl);
            }
        }
        __syncthreads();
    }

#pragma unroll
    for (int mi = 0; mi < 2; mi++)
#pragma unroll
        for (int rr = 0; rr < 2; rr++) {
            long long r = m0 + mbase + mi * 16 + rr * 8 + gID;
            long long p = (long long)parent[r] + 1;
            const float* ne = node_emb + p * FEATC;
            float* orow = g_h0 + r * FEATC;
#pragma unroll
            for (int nj = 0; nj < 8; nj++) {
                int c = nbase + nj * 8 + qid * 2;
                float2 bv = *(const float2*)(bp + c);
                float2 nv = *(const float2*)(ne + c);
                float2 o;
                o.x = leaky01(acc[mi][nj][rr * 2 + 0] + bv.x) + nv.x;
                o.y = leaky01(acc[mi][nj][rr * 2 + 1] + bv.y) + nv.y;
                *(float2*)(orow + c) = o;
            }
        }
}

// ---------------------------------------------------------------------------
// k_conv_mma<LAYER>: 128 dst rows per CTA, K-chunk = 32.
//  phase 1: Sagg fp32 in smem (gather-mean of 8 neighbors; L1 self-edge alg.)
//  phase 2: kc=0..3: acc1 += X(g_h0) @ W[:, 0:128].T
//           kc=4..7: acc1 += Agg @ W[:,128:256].T ; acc2 += Agg @ Wagg.T
//  phase 3: epilogue (leaky + rownorm for L0; plain sum for L1)
// Dynamic smem layout (bytes), total 106,496:
//   [0, 65536)        Sagg  float[128][128]
//   [65536, +10240)   Bh    bf16[128][BPAD2]   (overlaid by red/scales in ep.)
//   [75776, +10240)   Bl
//   [86016, +10240)   B2h
//   [96256, +10240)   B2l
// ---------------------------------------------------------------------------
#define BPAD2 40
#define CONV_SMEM_BYTES (65536 + 4 * 10240)

template <int LAYER>
__global__ __launch_bounds__(256) void k_conv_mma(
    const int*   __restrict__ nbr,   // random-edge srcs, nbr[8*dst + k]
    const float* __restrict__ b,     // [128]
    const float* __restrict__ bagg,  // [128]
    float*       __restrict__ dout)  // layer1 output
{
    extern __shared__ char smem[];
    float (*Sagg)[128] = (float(*)[128])smem;
    __nv_bfloat16* Bh  = (__nv_bfloat16*)(smem + 65536);
    __nv_bfloat16* Bl  = (__nv_bfloat16*)(smem + 75776);
    __nv_bfloat16* B2h = (__nv_bfloat16*)(smem + 86016);
    __nv_bfloat16* B2l = (__nv_bfloat16*)(smem + 96256);
    float* red    = (float*)(smem + 65536);          // [128][2], epilogue only
    float* scales = (float*)(smem + 65536 + 1024);   // [128]

    const int tid  = threadIdx.x;
    const int lane = tid & 31;
    const int warp = tid >> 5;
    const int wm   = warp & 3;
    const int wn   = warp >> 2;
    const int gID  = lane >> 2;
    const int qid  = lane & 3;
    const long long m0 = (long long)blockIdx.x * 128;
    const int mbase = wm * 32;
    const int nbase = wn * 64;
    const int WOFF  = (LAYER == 0) ? OFF_W0 : OFF_W1;
    const int AOFF  = (LAYER == 0) ? OFF_WAGG0 : OFF_WAGG1;
    const float* hsrc = (LAYER == 0) ? g_h0 : g_h1;
    float* outp = (LAYER == 0) ? g_h1 : dout;

    // ---- phase 1: aggregate neighbors into Sagg (fp32) ----
    for (int rr = warp; rr < 128; rr += 8) {
        long long drow = m0 + rr;
        const int* e = nbr + drow * 8;
        float4 s = make_float4(0.f, 0.f, 0.f, 0.f);
#pragma unroll
        for (int k = 0; k < 8; k++) {
            long long si = e[k];
            float4 v = *(const float4*)(hsrc + si * FEATC + lane * 4);
            s.x += v.x; s.y += v.y; s.z += v.z; s.w += v.w;
        }
        if (LAYER == 1) {
            float4 v1 = *(const float4*)(g_h1 + drow * FEATC + lane * 4);
            float4 v0 = *(const float4*)(g_h0 + drow * FEATC + lane * 4);
            s.x += v1.x - v0.x; s.y += v1.y - v0.y;
            s.z += v1.z - v0.z; s.w += v1.w - v0.w;
        }
        s.x *= 0.125f; s.y *= 0.125f; s.z *= 0.125f; s.w *= 0.125f;
        *(float4*)&Sagg[rr][lane * 4] = s;
    }
    __syncthreads();

    // ---- phase 2: GEMMs on HMMA, 8 K-chunks of 32 ----
    float acc1[2][8][4], acc2[2][8][4];
#pragma unroll
    for (int mi = 0; mi < 2; mi++)
#pragma unroll
        for (int nj = 0; nj < 8; nj++)
#pragma unroll
            for (int t = 0; t < 4; t++) { acc1[mi][nj][t] = 0.f; acc2[mi][nj][t] = 0.f; }

    for (int kc = 0; kc < 8; kc++) {
        const bool second = (kc >= 4);
        // stage W chunk: 128 rows x 32 cols, hi + lo
#pragma unroll
        for (int it = 0; it < 2; it++) {
            int g = tid + 256 * it;          // 0..511 uint4 groups
            int n = g >> 2;                  // 0..127
            int c = (g & 3) * 8;             // 0..24
            *(uint4*)&Bh[n * BPAD2 + c] = *(const uint4*)(g_wh + WOFF + n * CONTC + kc * 32 + c);
            *(uint4*)&Bl[n * BPAD2 + c] = *(const uint4*)(g_wl + WOFF + n * CONTC + kc * 32 + c);
        }
        if (second) {
#pragma unroll
            for (int it = 0; it < 2; it++) {
                int g = tid + 256 * it;
                int n = g >> 2;
                int c = (g & 3) * 8;
                *(uint4*)&B2h[n * BPAD2 + c] =
                    *(const uint4*)(g_wh + AOFF + n * FEATC + (kc - 4) * 32 + c);
                *(uint4*)&B2l[n * BPAD2 + c] =
                    *(const uint4*)(g_wl + AOFF + n * FEATC + (kc - 4) * 32 + c);
            }
        }
        __syncthreads();

#pragma unroll
        for (int s = 0; s < 2; s++) {        // two k16 steps per chunk
            uint32_t ah[2][4], al[2][4];
            if (!second) {
                const float* abase = g_h0 + (m0 + mbase + gID) * (long long)FEATC
                                   + kc * 32 + s * 16 + qid * 2;
#pragma unroll
                for (int mi = 0; mi < 2; mi++)
#pragma unroll
                    for (int rr = 0; rr < 2; rr++)
#pragma unroll
                        for (int kk = 0; kk < 2; kk++) {
                            float2 v = *(const float2*)(abase + (mi * 16 + rr * 8) * FEATC + kk * 8);
                            split2(v, ah[mi][rr + kk * 2], al[mi][rr + kk * 2]);
                        }
            } else {
                const float* abase = &Sagg[mbase + gID][(kc - 4) * 32 + s * 16 + qid * 2];
#pragma unroll
                for (int mi = 0; mi < 2; mi++)
#pragma unroll
                    for (int rr = 0; rr < 2; rr++)
#pragma unroll
                        for (int kk = 0; kk < 2; kk++) {
                            float2 v = *(const float2*)(abase + (mi * 16 + rr * 8) * 128 + kk * 8);
                            split2(v, ah[mi][rr + kk * 2], al[mi][rr + kk * 2]);
                        }
            }
#pragma unroll
            for (int nj = 0; nj < 8; nj++) {
                int n  = nbase + nj * 8 + gID;
                int cb = s * 16 + qid * 2;
                uint32_t bh[2], bl[2];
                bh[0] = *(const uint32_t*)&Bh[n * BPAD2 + cb];
                bh[1] = *(const uint32_t*)&Bh[n * BPAD2 + cb + 8];
                bl[0] = *(const uint32_t*)&Bl[n * BPAD2 + cb];
                bl[1] = *(const uint32_t*)&Bl[n * BPAD2 + cb + 8];
                mma16816(acc1[0][nj], ah[0], bh);
                mma16816(acc1[1][nj], ah[1], bh);
                mma16816(acc1[0][nj], al[0], bh);
                mma16816(acc1[1][nj], al[1], bh);
                mma16816(acc1[0][nj], ah[0], bl);
                mma16816(acc1[1][nj], ah[1], bl);
                if (second) {
                    uint32_t ch[2], cl[2];
                    ch[0] = *(const uint32_t*)&B2h[n * BPAD2 + cb];
                    ch[1] = *(const uint32_t*)&B2h[n * BPAD2 + cb + 8];
                    cl[0] = *(const uint32_t*)&B2l[n * BPAD2 + cb];
                    cl[1] = *(const uint32_t*)&B2l[n * BPAD2 + cb + 8];
                    mma16816(acc2[0][nj], ah[0], ch);
                    mma16816(acc2[1][nj], ah[1], ch);
                    mma16816(acc2[0][nj], al[0], ch);
                    mma16816(acc2[1][nj], al[1], ch);
                    mma16816(acc2[0][nj], ah[0], cl);
                    mma16816(acc2[1][nj], ah[1], cl);
                }
            }
        }
        __syncthreads();
    }

    // ---- phase 3: epilogue ----
    float ss[2][2] = {{0.f, 0.f}, {0.f, 0.f}};
#pragma unroll
    for (int mi = 0; mi < 2; mi++)
#pragma unroll
        for (int rr = 0; rr < 2; rr++)
#pragma unroll
            for (int nj = 0; nj < 8; nj++) {
                int c = nbase + nj * 8 + qid * 2;
#pragma unroll
                for (int k = 0; k < 2; k++) {
                    float t1 = acc1[mi][nj][rr * 2 + k] + b[c + k];
                    float t2 = acc2[mi][nj][rr * 2 + k] + bagg[c + k];
                    if (LAYER == 0) { t1 = leaky01(t1); t2 = leaky01(t2); }
                    float v = t1 + t2;
                    acc1[mi][nj][rr * 2 + k] = v;
                    if (LAYER == 0) ss[mi][rr] = fmaf(v, v, ss[mi][rr]);
                }
            }

    if (LAYER == 0) {
        // reduce ss over the 4 qid lanes (lanes gID*4 + qid share a row pair)
#pragma unroll
        for (int mi = 0; mi < 2; mi++)
#pragma unroll
            for (int rr = 0; rr < 2; rr++) {
                float v = ss[mi][rr];
                v += __shfl_xor_sync(0xFFFFFFFF, v, 1);
                v += __shfl_xor_sync(0xFFFFFFFF, v, 2);
                ss[mi][rr] = v;
            }
        if (qid == 0) {
#pragma unroll
            for (int mi = 0; mi < 2; mi++)
#pragma unroll
                for (int rr = 0; rr < 2; rr++) {
                    int rl = mbase + mi * 16 + rr * 8 + gID;
                    red[rl * 2 + wn] = ss[mi][rr];
                }
        }
        __syncthreads();
        if (tid < 128) {
            float s = red[tid * 2] + red[tid * 2 + 1];
            scales[tid] = 1.0f / fmaxf(sqrtf(s), 1e-6f);
        }
        __syncthreads();
#pragma unroll
        for (int mi = 0; mi < 2; mi++)
#pragma unroll
            for (int rr = 0; rr < 2; rr++) {
                int rl = mbase + mi * 16 + rr * 8 + gID;
                float sc = scales[rl];
                float* orow = outp + (m0 + rl) * (long long)FEATC;
#pragma unroll
                for (int nj = 0; nj < 8; nj++) {
                    int c = nbase + nj * 8 + qid * 2;
                    float2 o;
                    o.x = acc1[mi][nj][rr * 2 + 0] * sc;
                    o.y = acc1[mi][nj][rr * 2 + 1] * sc;
                    *(float2*)(orow + c) = o;
                }
            }
    } else {
#pragma unroll
        for (int mi = 0; mi < 2; mi++)
#pragma unroll
            for (int rr = 0; rr < 2; rr++) {
                int rl = mbase + mi * 16 + rr * 8 + gID;
                float* orow = outp + (m0 + rl) * (long long)FEATC;
#pragma unroll
                for (int nj = 0; nj < 8; nj++) {
                    int c = nbase + nj * 8 + qid * 2;
                    float2 o;
                    o.x = acc1[mi][nj][rr * 2 + 0];
                    o.y = acc1[mi][nj][rr * 2 + 1];
                    *(float2*)(orow + c) = o;
                }
            }
    }
}

// ---------------------------------------------------------------------------
// kernel_launch
// ---------------------------------------------------------------------------
extern "C" void kernel_launch(void* const* d_in, const int* in_sizes, int n_in,
                              void* d_out, int out_size)
{
    const float* node_emb = (const float*)d_in[0];
    const float* content0 = (const float*)d_in[1];
    const float* Wp    = (const float*)d_in[2];
    const float* bp    = (const float*)d_in[3];
    const float* W0    = (const float*)d_in[4];
    const float* b0    = (const float*)d_in[5];
    const float* Wagg0 = (const float*)d_in[6];
    const float* bagg0 = (const float*)d_in[7];
    const float* W1    = (const float*)d_in[8];
    const float* b1    = (const float*)d_in[9];
    const float* Wagg1 = (const float*)d_in[10];
    const float* bagg1 = (const float*)d_in[11];
    const int* parent0 = (const int*)d_in[12];
    const int* src0    = (const int*)d_in[13];
    const int* src1    = (const int*)d_in[15];
    float* out = (float*)d_out;

    cudaFuncSetAttribute(k_conv_mma<0>, cudaFuncAttributeMaxDynamicSharedMemorySize, CONV_SMEM_BYTES);
    cudaFuncSetAttribute(k_conv_mma<1>, cudaFuncAttributeMaxDynamicSharedMemorySize, CONV_SMEM_BYTES);

    k_prep<<<(W_TOTAL + 255) / 256, 256>>>(Wp, W0, Wagg0, W1, Wagg1);
    k_h0_mma<<<S0C / 128, 256>>>(content0, bp, node_emb, parent0);
    k_conv_mma<0><<<S1C / 128, 256, CONV_SMEM_BYTES>>>(src0 + S1C, b0, bagg0, nullptr);
    k_conv_mma<1><<<S2C / 128, 256, CONV_SMEM_BYTES>>>(src1 + S2C, b1, bagg1, out);
}

// round 8
// speedup vs baseline: 2.2489x; 1.2818x over previous
#include <cuda_runtime.h>
#include <cuda_bf16.h>
#include <cuda_fp16.h>
#include <cstdint>

// ---------------------------------------------------------------------------
// GraphSAGE with sampling, GB300 (compute_103 virtual arch -> no tcgen05).
// Round 7:
//  - k_h0_mma: fp16 single-term mma (error ~2^-12, fits 1e-3 budget), 16x128
//    warp tiles (no duplicated A loads). Tensor work per CTA drops 3x.
//  - conv kernels: unchanged from round 6 (bf16 3-term, passing, 106KB smem).
// Environment constraint learned: dynamic smem must stay <= ~116 KB.
// ---------------------------------------------------------------------------

#define FEATC 128
#define CONTC 256
#define S2C   8192
#define S1C   73728        /* S2*9 */
#define S0C   663552       /* S1*9 */

// weight hi/lo pool offsets (elements)
#define OFF_WP    0
#define OFF_W0    32768
#define OFF_WAGG0 65536
#define OFF_W1    81920
#define OFF_WAGG1 114688
#define W_TOTAL   131072

__device__ float g_h0[(long long)S0C * FEATC];   // 339.7 MB scratch
__device__ float g_h1[(long long)S1C * FEATC];   // 37.7 MB scratch
__device__ __nv_bfloat16 g_wh[W_TOTAL];
__device__ __nv_bfloat16 g_wl[W_TOTAL];
__device__ __half g_wp16[FEATC * CONTC];         // fp16 Wp for h0 GEMM

static __device__ __forceinline__ float leaky01(float x) {
    return x < 0.0f ? 0.1f * x : x;
}
static __device__ __forceinline__ uint32_t b2u(__nv_bfloat162 h) {
    return *reinterpret_cast<uint32_t*>(&h);
}
static __device__ __forceinline__ uint32_t h2u(__half2 h) {
    return *reinterpret_cast<uint32_t*>(&h);
}

// mma.sync m16n8k16 row.col f32.bf16.bf16.f32, accumulate in place
static __device__ __forceinline__ void mma16816(
    float* c, const uint32_t* a, const uint32_t* b)
{
    asm volatile(
        "mma.sync.aligned.m16n8k16.row.col.f32.bf16.bf16.f32 "
        "{%0,%1,%2,%3}, {%4,%5,%6,%7}, {%8,%9}, {%0,%1,%2,%3};"
        : "+f"(c[0]), "+f"(c[1]), "+f"(c[2]), "+f"(c[3])
        : "r"(a[0]), "r"(a[1]), "r"(a[2]), "r"(a[3]),
          "r"(b[0]), "r"(b[1]));
}

// mma.sync m16n8k16 row.col f32.f16.f16.f32, accumulate in place
static __device__ __forceinline__ void mma16816h(
    float* c, const uint32_t* a, const uint32_t* b)
{
    asm volatile(
        "mma.sync.aligned.m16n8k16.row.col.f32.f16.f16.f32 "
        "{%0,%1,%2,%3}, {%4,%5,%6,%7}, {%8,%9}, {%0,%1,%2,%3};"
        : "+f"(c[0]), "+f"(c[1]), "+f"(c[2]), "+f"(c[3])
        : "r"(a[0]), "r"(a[1]), "r"(a[2]), "r"(a[3]),
          "r"(b[0]), "r"(b[1]));
}

// split a float2 into bf16x2 hi + bf16x2 lo packed words
static __device__ __forceinline__ void split2(float2 v, uint32_t& hi, uint32_t& lo)
{
    __nv_bfloat162 h = __floats2bfloat162_rn(v.x, v.y);
    float rx = v.x - __bfloat162float(h.x);
    float ry = v.y - __bfloat162float(h.y);
    __nv_bfloat162 l = __floats2bfloat162_rn(rx, ry);
    hi = b2u(h); lo = b2u(l);
}

// ---------------------------------------------------------------------------
// k_prep: split all weights into bf16 hi/lo pool; also fp16 Wp for h0.
// ---------------------------------------------------------------------------
__global__ void k_prep(const float* __restrict__ Wp, const float* __restrict__ W0,
                       const float* __restrict__ Wagg0, const float* __restrict__ W1,
                       const float* __restrict__ Wagg1)
{
    int i = blockIdx.x * blockDim.x + threadIdx.x;
    if (i >= W_TOTAL) return;
    float v;
    if      (i < OFF_W0)    v = Wp[i - OFF_WP];
    else if (i < OFF_WAGG0) v = W0[i - OFF_W0];
    else if (i < OFF_W1)    v = Wagg0[i - OFF_WAGG0];
    else if (i < OFF_WAGG1) v = W1[i - OFF_W1];
    else                    v = Wagg1[i - OFF_WAGG1];
    __nv_bfloat16 h = __float2bfloat16_rn(v);
    g_wh[i] = h;
    g_wl[i] = __float2bfloat16_rn(v - __bfloat162float(h));
    if (i < FEATC * CONTC) g_wp16[i] = __float2half_rn(v);   // Wp region
}

// ---------------------------------------------------------------------------
// k_h0_mma: fp16 single-term GEMM. CTA tile 128x128, K=256 in chunks of 64.
// 8 warps, each owns 16 rows x 128 cols (no duplicated A loads).
// ---------------------------------------------------------------------------
#define BPAD 72

__global__ __launch_bounds__(256, 2) void k_h0_mma(
    const float* __restrict__ content,   // [S0,256]
    const float* __restrict__ bp,        // [128]
    const float* __restrict__ node_emb,  // [N+1,128]
    const int*   __restrict__ parent)    // [S0]
{
    __shared__ __half Bs[128 * BPAD];    // 18,432 B

    const int tid  = threadIdx.x;
    const int lane = tid & 31;
    const int warp = tid >> 5;           // 0..7
    const int gID  = lane >> 2;          // 0..7
    const int qid  = lane & 3;           // 0..3
    const long long m0 = (long long)blockIdx.x * 128;
    const int mbase = warp * 16;

    float acc[16][4];
#pragma unroll
    for (int nj = 0; nj < 16; nj++)
#pragma unroll
        for (int t = 0; t < 4; t++) acc[nj][t] = 0.0f;

    for (int kc = 0; kc < 4; kc++) {
        // stage Wp fp16 chunk: 128 n-rows x 64 k-cols
#pragma unroll
        for (int it = 0; it < 4; it++) {
            int g = tid + 256 * it;       // 0..1023 uint4 groups (8 halfs each)
            int n = g >> 3;               // 0..127
            int c = (g & 7) * 8;          // 0..56
            *(uint4*)&Bs[n * BPAD + c] = *(const uint4*)(g_wp16 + n * CONTC + kc * 64 + c);
        }
        __syncthreads();

#pragma unroll
        for (int s = 0; s < 4; s++) {
            // A fragment: rows gID / gID+8 of this warp's 16-row block
            uint32_t a[4];
            const float* abase = content + (m0 + mbase + gID) * (long long)CONTC
                               + kc * 64 + s * 16 + qid * 2;
#pragma unroll
            for (int rr = 0; rr < 2; rr++)
#pragma unroll
                for (int kk = 0; kk < 2; kk++) {
                    float2 v = *(const float2*)(abase + rr * 8 * CONTC + kk * 8);
                    a[rr + kk * 2] = h2u(__float22half2_rn(v));
                }
#pragma unroll
            for (int nj = 0; nj < 16; nj++) {
                int n  = nj * 8 + gID;
                int cb = s * 16 + qid * 2;
                uint32_t b[2];
                b[0] = *(const uint32_t*)&Bs[n * BPAD + cb];
                b[1] = *(const uint32_t*)&Bs[n * BPAD + cb + 8];
                mma16816h(acc[nj], a, b);
            }
        }
        __syncthreads();
    }

    // epilogue: bias + leaky + node_emb gather -> g_h0
#pragma unroll
    for (int rr = 0; rr < 2; rr++) {
        long long r = m0 + mbase + rr * 8 + gID;
        long long p = (long long)parent[r] + 1;
        const float* ne = node_emb + p * FEATC;
        float* orow = g_h0 + r * FEATC;
#pragma unroll
        for (int nj = 0; nj < 16; nj++) {
            int c = nj * 8 + qid * 2;
            float2 bv = *(const float2*)(bp + c);
            float2 nv = *(const float2*)(ne + c);
            float2 o;
            o.x = leaky01(acc[nj][rr * 2 + 0] + bv.x) + nv.x;
            o.y = leaky01(acc[nj][rr * 2 + 1] + bv.y) + nv.y;
            *(float2*)(orow + c) = o;
        }
    }
}

// ---------------------------------------------------------------------------
// k_conv_mma<LAYER>: unchanged from round 6 (passing). 128 dst rows per CTA,
// K-chunk = 32, bf16 3-term. Dynamic smem 106,496 B (< 116 KB env limit).
// ---------------------------------------------------------------------------
#define BPAD2 40
#define CONV_SMEM_BYTES (65536 + 4 * 10240)

template <int LAYER>
__global__ __launch_bounds__(256) void k_conv_mma(
    const int*   __restrict__ nbr,   // random-edge srcs, nbr[8*dst + k]
    const float* __restrict__ b,     // [128]
    const float* __restrict__ bagg,  // [128]
    float*       __restrict__ dout)  // layer1 output
{
    extern __shared__ char smem[];
    float (*Sagg)[128] = (float(*)[128])smem;
    __nv_bfloat16* Bh  = (__nv_bfloat16*)(smem + 65536);
    __nv_bfloat16* Bl  = (__nv_bfloat16*)(smem + 75776);
    __nv_bfloat16* B2h = (__nv_bfloat16*)(smem + 86016);
    __nv_bfloat16* B2l = (__nv_bfloat16*)(smem + 96256);
    float* red    = (float*)(smem + 65536);          // [128][2], epilogue only
    float* scales = (float*)(smem + 65536 + 1024);   // [128]

    const int tid  = threadIdx.x;
    const int lane = tid & 31;
    const int warp = tid >> 5;
    const int wm   = warp & 3;
    const int wn   = warp >> 2;
    const int gID  = lane >> 2;
    const int qid  = lane & 3;
    const long long m0 = (long long)blockIdx.x * 128;
    const int mbase = wm * 32;
    const int nbase = wn * 64;
    const int WOFF  = (LAYER == 0) ? OFF_W0 : OFF_W1;
    const int AOFF  = (LAYER == 0) ? OFF_WAGG0 : OFF_WAGG1;
    const float* hsrc = (LAYER == 0) ? g_h0 : g_h1;
    float* outp = (LAYER == 0) ? g_h1 : dout;

    // ---- phase 1: aggregate neighbors into Sagg (fp32) ----
    for (int rr = warp; rr < 128; rr += 8) {
        long long drow = m0 + rr;
        const int* e = nbr + drow * 8;
        float4 s = make_float4(0.f, 0.f, 0.f, 0.f);
#pragma unroll
        for (int k = 0; k < 8; k++) {
            long long si = e[k];
            float4 v = *(const float4*)(hsrc + si * FEATC + lane * 4);
            s.x += v.x; s.y += v.y; s.z += v.z; s.w += v.w;
        }
        if (LAYER == 1) {
            float4 v1 = *(const float4*)(g_h1 + drow * FEATC + lane * 4);
            float4 v0 = *(const float4*)(g_h0 + drow * FEATC + lane * 4);
            s.x += v1.x - v0.x; s.y += v1.y - v0.y;
            s.z += v1.z - v0.z; s.w += v1.w - v0.w;
        }
        s.x *= 0.125f; s.y *= 0.125f; s.z *= 0.125f; s.w *= 0.125f;
        *(float4*)&Sagg[rr][lane * 4] = s;
    }
    __syncthreads();

    // ---- phase 2: GEMMs on HMMA, 8 K-chunks of 32 ----
    float acc1[2][8][4], acc2[2][8][4];
#pragma unroll
    for (int mi = 0; mi < 2; mi++)
#pragma unroll
        for (int nj = 0; nj < 8; nj++)
#pragma unroll
            for (int t = 0; t < 4; t++) { acc1[mi][nj][t] = 0.f; acc2[mi][nj][t] = 0.f; }

    for (int kc = 0; kc < 8; kc++) {
        const bool second = (kc >= 4);
        // stage W chunk: 128 rows x 32 cols, hi + lo
#pragma unroll
        for (int it = 0; it < 2; it++) {
            int g = tid + 256 * it;          // 0..511 uint4 groups
            int n = g >> 2;                  // 0..127
            int c = (g & 3) * 8;             // 0..24
            *(uint4*)&Bh[n * BPAD2 + c] = *(const uint4*)(g_wh + WOFF + n * CONTC + kc * 32 + c);
            *(uint4*)&Bl[n * BPAD2 + c] = *(const uint4*)(g_wl + WOFF + n * CONTC + kc * 32 + c);
        }
        if (second) {
#pragma unroll
            for (int it = 0; it < 2; it++) {
                int g = tid + 256 * it;
                int n = g >> 2;
                int c = (g & 3) * 8;
                *(uint4*)&B2h[n * BPAD2 + c] =
                    *(const uint4*)(g_wh + AOFF + n * FEATC + (kc - 4) * 32 + c);
                *(uint4*)&B2l[n * BPAD2 + c] =
                    *(const uint4*)(g_wl + AOFF + n * FEATC + (kc - 4) * 32 + c);
            }
        }
        __syncthreads();

#pragma unroll
        for (int s = 0; s < 2; s++) {        // two k16 steps per chunk
            uint32_t ah[2][4], al[2][4];
            if (!second) {
                const float* abase = g_h0 + (m0 + mbase + gID) * (long long)FEATC
                                   + kc * 32 + s * 16 + qid * 2;
#pragma unroll
                for (int mi = 0; mi < 2; mi++)
#pragma unroll
                    for (int rr = 0; rr < 2; rr++)
#pragma unroll
                        for (int kk = 0; kk < 2; kk++) {
                            float2 v = *(const float2*)(abase + (mi * 16 + rr * 8) * FEATC + kk * 8);
                            split2(v, ah[mi][rr + kk * 2], al[mi][rr + kk * 2]);
                        }
            } else {
                const float* abase = &Sagg[mbase + gID][(kc - 4) * 32 + s * 16 + qid * 2];
#pragma unroll
                for (int mi = 0; mi < 2; mi++)
#pragma unroll
                    for (int rr = 0; rr < 2; rr++)
#pragma unroll
                        for (int kk = 0; kk < 2; kk++) {
                            float2 v = *(const float2*)(abase + (mi * 16 + rr * 8) * 128 + kk * 8);
                            split2(v, ah[mi][rr + kk * 2], al[mi][rr + kk * 2]);
                        }
            }
#pragma unroll
            for (int nj = 0; nj < 8; nj++) {
                int n  = nbase + nj * 8 + gID;
                int cb = s * 16 + qid * 2;
                uint32_t bh[2], bl[2];
                bh[0] = *(const uint32_t*)&Bh[n * BPAD2 + cb];
                bh[1] = *(const uint32_t*)&Bh[n * BPAD2 + cb + 8];
                bl[0] = *(const uint32_t*)&Bl[n * BPAD2 + cb];
                bl[1] = *(const uint32_t*)&Bl[n * BPAD2 + cb + 8];
                mma16816(acc1[0][nj], ah[0], bh);
                mma16816(acc1[1][nj], ah[1], bh);
                mma16816(acc1[0][nj], al[0], bh);
                mma16816(acc1[1][nj], al[1], bh);
                mma16816(acc1[0][nj], ah[0], bl);
                mma16816(acc1[1][nj], ah[1], bl);
                if (second) {
                    uint32_t ch[2], cl[2];
                    ch[0] = *(const uint32_t*)&B2h[n * BPAD2 + cb];
                    ch[1] = *(const uint32_t*)&B2h[n * BPAD2 + cb + 8];
                    cl[0] = *(const uint32_t*)&B2l[n * BPAD2 + cb];
                    cl[1] = *(const uint32_t*)&B2l[n * BPAD2 + cb + 8];
                    mma16816(acc2[0][nj], ah[0], ch);
                    mma16816(acc2[1][nj], ah[1], ch);
                    mma16816(acc2[0][nj], al[0], ch);
                    mma16816(acc2[1][nj], al[1], ch);
                    mma16816(acc2[0][nj], ah[0], cl);
                    mma16816(acc2[1][nj], ah[1], cl);
                }
            }
        }
        __syncthreads();
    }

    // ---- phase 3: epilogue ----
    float ss[2][2] = {{0.f, 0.f}, {0.f, 0.f}};
#pragma unroll
    for (int mi = 0; mi < 2; mi++)
#pragma unroll
        for (int rr = 0; rr < 2; rr++)
#pragma unroll
            for (int nj = 0; nj < 8; nj++) {
                int c = nbase + nj * 8 + qid * 2;
#pragma unroll
                for (int k = 0; k < 2; k++) {
                    float t1 = acc1[mi][nj][rr * 2 + k] + b[c + k];
                    float t2 = acc2[mi][nj][rr * 2 + k] + bagg[c + k];
                    if (LAYER == 0) { t1 = leaky01(t1); t2 = leaky01(t2); }
                    float v = t1 + t2;
                    acc1[mi][nj][rr * 2 + k] = v;
                    if (LAYER == 0) ss[mi][rr] = fmaf(v, v, ss[mi][rr]);
                }
            }

    if (LAYER == 0) {
#pragma unroll
        for (int mi = 0; mi < 2; mi++)
#pragma unroll
            for (int rr = 0; rr < 2; rr++) {
                float v = ss[mi][rr];
                v += __shfl_xor_sync(0xFFFFFFFF, v, 1);
                v += __shfl_xor_sync(0xFFFFFFFF, v, 2);
                ss[mi][rr] = v;
            }
        if (qid == 0) {
#pragma unroll
            for (int mi = 0; mi < 2; mi++)
#pragma unroll
                for (int rr = 0; rr < 2; rr++) {
                    int rl = mbase + mi * 16 + rr * 8 + gID;
                    red[rl * 2 + wn] = ss[mi][rr];
                }
        }
        __syncthreads();
        if (tid < 128) {
            float s = red[tid * 2] + red[tid * 2 + 1];
            scales[tid] = 1.0f / fmaxf(sqrtf(s), 1e-6f);
        }
        __syncthreads();
#pragma unroll
        for (int mi = 0; mi < 2; mi++)
#pragma unroll
            for (int rr = 0; rr < 2; rr++) {
                int rl = mbase + mi * 16 + rr * 8 + gID;
                float sc = scales[rl];
                float* orow = outp + (m0 + rl) * (long long)FEATC;
#pragma unroll
                for (int nj = 0; nj < 8; nj++) {
                    int c = nbase + nj * 8 + qid * 2;
                    float2 o;
                    o.x = acc1[mi][nj][rr * 2 + 0] * sc;
                    o.y = acc1[mi][nj][rr * 2 + 1] * sc;
                    *(float2*)(orow + c) = o;
                }
            }
    } else {
#pragma unroll
        for (int mi = 0; mi < 2; mi++)
#pragma unroll
            for (int rr = 0; rr < 2; rr++) {
                int rl = mbase + mi * 16 + rr * 8 + gID;
                float* orow = outp + (m0 + rl) * (long long)FEATC;
#pragma unroll
                for (int nj = 0; nj < 8; nj++) {
                    int c = nbase + nj * 8 + qid * 2;
                    float2 o;
                    o.x = acc1[mi][nj][rr * 2 + 0];
                    o.y = acc1[mi][nj][rr * 2 + 1];
                    *(float2*)(orow + c) = o;
                }
            }
    }
}

// ---------------------------------------------------------------------------
// kernel_launch
// ---------------------------------------------------------------------------
extern "C" void kernel_launch(void* const* d_in, const int* in_sizes, int n_in,
                              void* d_out, int out_size)
{
    const float* node_emb = (const float*)d_in[0];
    const float* content0 = (const float*)d_in[1];
    const float* Wp    = (const float*)d_in[2];
    const float* bp    = (const float*)d_in[3];
    const float* W0    = (const float*)d_in[4];
    const float* b0    = (const float*)d_in[5];
    const float* Wagg0 = (const float*)d_in[6];
    const float* bagg0 = (const float*)d_in[7];
    const float* W1    = (const float*)d_in[8];
    const float* b1    = (const float*)d_in[9];
    const float* Wagg1 = (const float*)d_in[10];
    const float* bagg1 = (const float*)d_in[11];
    const int* parent0 = (const int*)d_in[12];
    const int* src0    = (const int*)d_in[13];
    const int* src1    = (const int*)d_in[15];
    float* out = (float*)d_out;

    cudaFuncSetAttribute(k_conv_mma<0>, cudaFuncAttributeMaxDynamicSharedMemorySize, CONV_SMEM_BYTES);
    cudaFuncSetAttribute(k_conv_mma<1>, cudaFuncAttributeMaxDynamicSharedMemorySize, CONV_SMEM_BYTES);

    k_prep<<<(W_TOTAL + 255) / 256, 256>>>(Wp, W0, Wagg0, W1, Wagg1);
    k_h0_mma<<<S0C / 128, 256>>>(content0, bp, node_emb, parent0);
    k_conv_mma<0><<<S1C / 128, 256, CONV_SMEM_BYTES>>>(src0 + S1C, b0, bagg0, nullptr);
    k_conv_mma<1><<<S2C / 128, 256, CONV_SMEM_BYTES>>>(src1 + S2C, b1, bagg1, out);
}

// round 9
// speedup vs baseline: 2.7090x; 1.2046x over previous
#include <cuda_runtime.h>
#include <cuda_fp16.h>
#include <cstdint>

// ---------------------------------------------------------------------------
// GraphSAGE with sampling, GB300 (compute_103 virtual arch -> no tcgen05).
// Round 9:
//  - h0 / h1 stored fp16 (halves h0 stores + conv gathers; makes conv A
//    operands exact in fp16).
//  - conv GEMMs: fp16 A-exact, weights split fp16 hi/lo (2-term, ~2^-24 wt err)
//  - conv CTAs 64 rows: ~110 regs -> 2 CTAs/SM (was 176 regs -> 1 CTA/SM)
// Env constraint: dynamic smem <= ~116 KB (conv uses 58,368 B).
// ---------------------------------------------------------------------------

#define FEATC 128
#define CONTC 256
#define S2C   8192
#define S1C   73728        /* S2*9 */
#define S0C   663552       /* S1*9 */

// weight pool offsets (elements)
#define OFF_WP    0
#define OFF_W0    32768
#define OFF_WAGG0 65536
#define OFF_W1    81920
#define OFF_WAGG1 114688
#define W_TOTAL   131072

__device__ __half g_h0h[(long long)S0C * FEATC];   // 169.9 MB scratch
__device__ __half g_h1h[(long long)S1C * FEATC];   // 18.9 MB scratch
__device__ __half g_w16h[W_TOTAL];                 // fp16 hi of all weights
__device__ __half g_w16l[W_TOTAL];                 // fp16 lo (residual)

static __device__ __forceinline__ float leaky01(float x) {
    return x < 0.0f ? 0.1f * x : x;
}
static __device__ __forceinline__ uint32_t h2u(__half2 h) {
    return *reinterpret_cast<uint32_t*>(&h);
}

// mma.sync m16n8k16 row.col f32.f16.f16.f32, accumulate in place
static __device__ __forceinline__ void mma16816h(
    float* c, const uint32_t* a, const uint32_t* b)
{
    asm volatile(
        "mma.sync.aligned.m16n8k16.row.col.f32.f16.f16.f32 "
        "{%0,%1,%2,%3}, {%4,%5,%6,%7}, {%8,%9}, {%0,%1,%2,%3};"
        : "+f"(c[0]), "+f"(c[1]), "+f"(c[2]), "+f"(c[3])
        : "r"(a[0]), "r"(a[1]), "r"(a[2]), "r"(a[3]),
          "r"(b[0]), "r"(b[1]));
}

// ---------------------------------------------------------------------------
// k_prep: fp16 hi/lo split of all weight matrices.
// ---------------------------------------------------------------------------
__global__ void k_prep(const float* __restrict__ Wp, const float* __restrict__ W0,
                       const float* __restrict__ Wagg0, const float* __restrict__ W1,
                       const float* __restrict__ Wagg1)
{
    int i = blockIdx.x * blockDim.x + threadIdx.x;
    if (i >= W_TOTAL) return;
    float v;
    if      (i < OFF_W0)    v = Wp[i - OFF_WP];
    else if (i < OFF_WAGG0) v = W0[i - OFF_W0];
    else if (i < OFF_W1)    v = Wagg0[i - OFF_WAGG0];
    else if (i < OFF_WAGG1) v = W1[i - OFF_W1];
    else                    v = Wagg1[i - OFF_WAGG1];
    __half h = __float2half_rn(v);
    g_w16h[i] = h;
    g_w16l[i] = __float2half_rn(v - __half2float(h));
}

// ---------------------------------------------------------------------------
// k_h0_mma: fp16 single-term GEMM (round-8-proven). CTA 128x128, K chunks 64.
// 8 warps x (16 rows x 128 cols). Output stored fp16 to g_h0h.
// ---------------------------------------------------------------------------
#define BPAD 72

__global__ __launch_bounds__(256, 2) void k_h0_mma(
    const float* __restrict__ content,   // [S0,256]
    const float* __restrict__ bp,        // [128]
    const float* __restrict__ node_emb,  // [N+1,128]
    const int*   __restrict__ parent)    // [S0]
{
    __shared__ __half Bs[128 * BPAD];    // 18,432 B

    const int tid  = threadIdx.x;
    const int lane = tid & 31;
    const int warp = tid >> 5;           // 0..7
    const int gID  = lane >> 2;          // 0..7
    const int qid  = lane & 3;           // 0..3
    const long long m0 = (long long)blockIdx.x * 128;
    const int mbase = warp * 16;

    float acc[16][4];
#pragma unroll
    for (int nj = 0; nj < 16; nj++)
#pragma unroll
        for (int t = 0; t < 4; t++) acc[nj][t] = 0.0f;

    for (int kc = 0; kc < 4; kc++) {
#pragma unroll
        for (int it = 0; it < 4; it++) {
            int g = tid + 256 * it;
            int n = g >> 3;
            int c = (g & 7) * 8;
            *(uint4*)&Bs[n * BPAD + c] =
                *(const uint4*)(g_w16h + OFF_WP + n * CONTC + kc * 64 + c);
        }
        __syncthreads();

#pragma unroll
        for (int s = 0; s < 4; s++) {
            uint32_t a[4];
            const float* abase = content + (m0 + mbase + gID) * (long long)CONTC
                               + kc * 64 + s * 16 + qid * 2;
#pragma unroll
            for (int rr = 0; rr < 2; rr++)
#pragma unroll
                for (int kk = 0; kk < 2; kk++) {
                    float2 v = *(const float2*)(abase + rr * 8 * CONTC + kk * 8);
                    a[rr + kk * 2] = h2u(__float22half2_rn(v));
                }
#pragma unroll
            for (int nj = 0; nj < 16; nj++) {
                int n  = nj * 8 + gID;
                int cb = s * 16 + qid * 2;
                uint32_t b[2];
                b[0] = *(const uint32_t*)&Bs[n * BPAD + cb];
                b[1] = *(const uint32_t*)&Bs[n * BPAD + cb + 8];
                mma16816h(acc[nj], a, b);
            }
        }
        __syncthreads();
    }

    // epilogue: bias + leaky + node_emb gather -> g_h0h (fp16)
#pragma unroll
    for (int rr = 0; rr < 2; rr++) {
        long long r = m0 + mbase + rr * 8 + gID;
        long long p = (long long)parent[r] + 1;
        const float* ne = node_emb + p * FEATC;
        __half* orow = g_h0h + r * FEATC;
#pragma unroll
        for (int nj = 0; nj < 16; nj++) {
            int c = nj * 8 + qid * 2;
            float2 bv = *(const float2*)(bp + c);
            float2 nv = *(const float2*)(ne + c);
            float ox = leaky01(acc[nj][rr * 2 + 0] + bv.x) + nv.x;
            float oy = leaky01(acc[nj][rr * 2 + 1] + bv.y) + nv.y;
            *(__half2*)(orow + c) = __floats2half2_rn(ox, oy);
        }
    }
}

// ---------------------------------------------------------------------------
// k_conv_mma<LAYER>: 64 dst rows per CTA, fp16 A-exact / weight 2-term.
//  phase 1: Sagg fp16 in smem (gather-mean of 8 fp16 neighbors)
//  phase 2: kc=0..3: acc1 += X(g_h0h) @ W[:,0:128].T
//           kc=4..7: acc1 += Agg @ W[:,128:256].T ; acc2 += Agg @ Wagg.T
//  phase 3: epilogue (leaky + rownorm -> g_h1h for L0; fp32 sum -> dout for L1)
// Dynamic smem (bytes), total 58,368:
//   [0, 17408)        Sagg  half[64][136]
//   [17408, +10240)   Bh    half[128][40]   (overlaid by red/scales in epilogue)
//   [27648, +10240)   Bl
//   [37888, +10240)   B2h
//   [48128, +10240)   B2l
// ---------------------------------------------------------------------------
#define CPITCH 136
#define BPAD2  40
#define CONV_SMEM_BYTES (17408 + 4 * 10240)

template <int LAYER>
__global__ __launch_bounds__(256, 2) void k_conv_mma(
    const int*   __restrict__ nbr,   // random-edge srcs, nbr[8*dst + k]
    const float* __restrict__ b,     // [128]
    const float* __restrict__ bagg,  // [128]
    float*       __restrict__ dout)  // layer1 output
{
    extern __shared__ char smem[];
    __half* Sagg = (__half*)smem;                    // [64][CPITCH]
    __half* Bh   = (__half*)(smem + 17408);
    __half* Bl   = (__half*)(smem + 27648);
    __half* B2h  = (__half*)(smem + 37888);
    __half* B2l  = (__half*)(smem + 48128);
    float* red    = (float*)(smem + 17408);          // [64][2], epilogue only
    float* scales = (float*)(smem + 17408 + 512);    // [64]

    const int tid  = threadIdx.x;
    const int lane = tid & 31;
    const int warp = tid >> 5;
    const int wm   = warp & 3;           // 16-row m-block
    const int wn   = warp >> 2;          // 64-col n-block
    const int gID  = lane >> 2;
    const int qid  = lane & 3;
    const long long m0 = (long long)blockIdx.x * 64;
    const int mbase = wm * 16;
    const int nbase = wn * 64;
    const int WOFF  = (LAYER == 0) ? OFF_W0 : OFF_W1;
    const int AOFF  = (LAYER == 0) ? OFF_WAGG0 : OFF_WAGG1;
    const __half* hsrc = (LAYER == 0) ? g_h0h : g_h1h;

    // ---- phase 1: aggregate 8 neighbors (fp16 in, fp32 sum, fp16 out) ----
    for (int rr = warp; rr < 64; rr += 8) {
        long long drow = m0 + rr;
        const int* e = nbr + drow * 8;
        float4 s = make_float4(0.f, 0.f, 0.f, 0.f);
#pragma unroll
        for (int k = 0; k < 8; k++) {
            long long si = e[k];
            uint2 u = *(const uint2*)(hsrc + si * FEATC + lane * 4);
            float2 f0 = __half22float2(*(__half2*)&u.x);
            float2 f1 = __half22float2(*(__half2*)&u.y);
            s.x += f0.x; s.y += f0.y; s.z += f1.x; s.w += f1.y;
        }
        if (LAYER == 1) {
            uint2 u1 = *(const uint2*)(g_h1h + drow * FEATC + lane * 4);
            uint2 u0 = *(const uint2*)(g_h0h + drow * FEATC + lane * 4);
            float2 a0 = __half22float2(*(__half2*)&u1.x);
            float2 a1 = __half22float2(*(__half2*)&u1.y);
            float2 c0 = __half22float2(*(__half2*)&u0.x);
            float2 c1 = __half22float2(*(__half2*)&u0.y);
            s.x += a0.x - c0.x; s.y += a0.y - c0.y;
            s.z += a1.x - c1.x; s.w += a1.y - c1.y;
        }
        s.x *= 0.125f; s.y *= 0.125f; s.z *= 0.125f; s.w *= 0.125f;
        uint2 o;
        *(__half2*)&o.x = __floats2half2_rn(s.x, s.y);
        *(__half2*)&o.y = __floats2half2_rn(s.z, s.w);
        *(uint2*)&Sagg[rr * CPITCH + lane * 4] = o;
    }
    __syncthreads();

    // ---- phase 2: GEMMs, 8 K-chunks of 32, A exact / B 2-term ----
    float acc1[8][4], acc2[8][4];
#pragma unroll
    for (int nj = 0; nj < 8; nj++)
#pragma unroll
        for (int t = 0; t < 4; t++) { acc1[nj][t] = 0.f; acc2[nj][t] = 0.f; }

    for (int kc = 0; kc < 8; kc++) {
        const bool second = (kc >= 4);
#pragma unroll
        for (int it = 0; it < 2; it++) {
            int g = tid + 256 * it;          // 0..511 uint4 groups
            int n = g >> 2;                  // 0..127
            int c = (g & 3) * 8;             // 0..24
            *(uint4*)&Bh[n * BPAD2 + c] = *(const uint4*)(g_w16h + WOFF + n * CONTC + kc * 32 + c);
            *(uint4*)&Bl[n * BPAD2 + c] = *(const uint4*)(g_w16l + WOFF + n * CONTC + kc * 32 + c);
        }
        if (second) {
#pragma unroll
            for (int it = 0; it < 2; it++) {
                int g = tid + 256 * it;
                int n = g >> 2;
                int c = (g & 3) * 8;
                *(uint4*)&B2h[n * BPAD2 + c] =
                    *(const uint4*)(g_w16h + AOFF + n * FEATC + (kc - 4) * 32 + c);
                *(uint4*)&B2l[n * BPAD2 + c] =
                    *(const uint4*)(g_w16l + AOFF + n * FEATC + (kc - 4) * 32 + c);
            }
        }
        __syncthreads();

#pragma unroll
        for (int s = 0; s < 2; s++) {
            uint32_t a[4];
            if (!second) {
                const __half* ab = g_h0h + (m0 + mbase + gID) * (long long)FEATC
                                 + kc * 32 + s * 16 + qid * 2;
#pragma unroll
                for (int rr = 0; rr < 2; rr++)
#pragma unroll
                    for (int kk = 0; kk < 2; kk++)
                        a[rr + kk * 2] = *(const uint32_t*)(ab + rr * 8 * FEATC + kk * 8);
            } else {
                const __half* ab = Sagg + (mbase + gID) * CPITCH
                                 + (kc - 4) * 32 + s * 16 + qid * 2;
#pragma unroll
                for (int rr = 0; rr < 2; rr++)
#pragma unroll
                    for (int kk = 0; kk < 2; kk++)
                        a[rr + kk * 2] = *(const uint32_t*)(ab + rr * 8 * CPITCH + kk * 8);
            }
#pragma unroll
            for (int nj = 0; nj < 8; nj++) {
                int n  = nbase + nj * 8 + gID;
                int cb = s * 16 + qid * 2;
                uint32_t bh[2], bl[2];
                bh[0] = *(const uint32_t*)&Bh[n * BPAD2 + cb];
                bh[1] = *(const uint32_t*)&Bh[n * BPAD2 + cb + 8];
                bl[0] = *(const uint32_t*)&Bl[n * BPAD2 + cb];
                bl[1] = *(const uint32_t*)&Bl[n * BPAD2 + cb + 8];
                mma16816h(acc1[nj], a, bh);
                mma16816h(acc1[nj], a, bl);
                if (second) {
                    uint32_t ch[2], cl[2];
                    ch[0] = *(const uint32_t*)&B2h[n * BPAD2 + cb];
                    ch[1] = *(const uint32_t*)&B2h[n * BPAD2 + cb + 8];
                    cl[0] = *(const uint32_t*)&B2l[n * BPAD2 + cb];
                    cl[1] = *(const uint32_t*)&B2l[n * BPAD2 + cb + 8];
                    mma16816h(acc2[nj], a, ch);
                    mma16816h(acc2[nj], a, cl);
                }
            }
        }
        __syncthreads();
    }

    // ---- phase 3: epilogue ----
    float ss[2] = {0.f, 0.f};
#pragma unroll
    for (int rr = 0; rr < 2; rr++)
#pragma unroll
        for (int nj = 0; nj < 8; nj++) {
            int c = nbase + nj * 8 + qid * 2;
#pragma unroll
            for (int k = 0; k < 2; k++) {
                float t1 = acc1[nj][rr * 2 + k] + b[c + k];
                float t2 = acc2[nj][rr * 2 + k] + bagg[c + k];
                if (LAYER == 0) { t1 = leaky01(t1); t2 = leaky01(t2); }
                float v = t1 + t2;
                acc1[nj][rr * 2 + k] = v;
                if (LAYER == 0) ss[rr] = fmaf(v, v, ss[rr]);
            }
        }

    if (LAYER == 0) {
        // reduce over qid lanes, then across the 2 n-block warps via smem
#pragma unroll
        for (int rr = 0; rr < 2; rr++) {
            float v = ss[rr];
            v += __shfl_xor_sync(0xFFFFFFFF, v, 1);
            v += __shfl_xor_sync(0xFFFFFFFF, v, 2);
            ss[rr] = v;
        }
        if (qid == 0) {
#pragma unroll
            for (int rr = 0; rr < 2; rr++) {
                int rl = mbase + rr * 8 + gID;
                red[rl * 2 + wn] = ss[rr];
            }
        }
        __syncthreads();
        if (tid < 64) {
            float s = red[tid * 2] + red[tid * 2 + 1];
            scales[tid] = 1.0f / fmaxf(sqrtf(s), 1e-6f);
        }
        __syncthreads();
#pragma unroll
        for (int rr = 0; rr < 2; rr++) {
            int rl = mbase + rr * 8 + gID;
            float sc = scales[rl];
            __half* orow = g_h1h + (m0 + rl) * (long long)FEATC;
#pragma unroll
            for (int nj = 0; nj < 8; nj++) {
                int c = nbase + nj * 8 + qid * 2;
                *(__half2*)(orow + c) = __floats2half2_rn(
                    acc1[nj][rr * 2 + 0] * sc, acc1[nj][rr * 2 + 1] * sc);
            }
        }
    } else {
#pragma unroll
        for (int rr = 0; rr < 2; rr++) {
            int rl = mbase + rr * 8 + gID;
            float* orow = dout + (m0 + rl) * (long long)FEATC;
#pragma unroll
            for (int nj = 0; nj < 8; nj++) {
                int c = nbase + nj * 8 + qid * 2;
                float2 o;
                o.x = acc1[nj][rr * 2 + 0];
                o.y = acc1[nj][rr * 2 + 1];
                *(float2*)(orow + c) = o;
            }
        }
    }
}

// ---------------------------------------------------------------------------
// kernel_launch
// ---------------------------------------------------------------------------
extern "C" void kernel_launch(void* const* d_in, const int* in_sizes, int n_in,
                              void* d_out, int out_size)
{
    const float* node_emb = (const float*)d_in[0];
    const float* content0 = (const float*)d_in[1];
    const float* Wp    = (const float*)d_in[2];
    const float* bp    = (const float*)d_in[3];
    const float* W0    = (const float*)d_in[4];
    const float* b0    = (const float*)d_in[5];
    const float* Wagg0 = (const float*)d_in[6];
    const float* bagg0 = (const float*)d_in[7];
    const float* W1    = (const float*)d_in[8];
    const float* b1    = (const float*)d_in[9];
    const float* Wagg1 = (const float*)d_in[10];
    const float* bagg1 = (const float*)d_in[11];
    const int* parent0 = (const int*)d_in[12];
    const int* src0    = (const int*)d_in[13];
    const int* src1    = (const int*)d_in[15];
    float* out = (float*)d_out;

    cudaFuncSetAttribute(k_conv_mma<0>, cudaFuncAttributeMaxDynamicSharedMemorySize, CONV_SMEM_BYTES);
    cudaFuncSetAttribute(k_conv_mma<1>, cudaFuncAttributeMaxDynamicSharedMemorySize, CONV_SMEM_BYTES);

    k_prep<<<(W_TOTAL + 255) / 256, 256>>>(Wp, W0, Wagg0, W1, Wagg1);
    k_h0_mma<<<S0C / 128, 256>>>(content0, bp, node_emb, parent0);
    k_conv_mma<0><<<S1C / 64, 256, CONV_SMEM_BYTES>>>(src0 + S1C, b0, bagg0, nullptr);
    k_conv_mma<1><<<S2C / 64, 256, CONV_SMEM_BYTES>>>(src1 + S2C, b1, bagg1, out);
}

// round 10
// speedup vs baseline: 3.3008x; 1.2185x over previous
#include <cuda_runtime.h>
#include <cuda_fp16.h>
#include <cstdint>

// ---------------------------------------------------------------------------
// GraphSAGE with sampling, GB300 (compute_103 virtual arch -> no tcgen05).
// Round 10:
//  - single-term fp16 everywhere (calibrated error ~5e-4 < 1e-3 budget)
//  - h0: whole Wp resident in smem -> ONE sync in mainloop
//  - conv: K-chunk 64, single-term -> half the MMAs/staging of round 9
// Env constraint: dynamic smem <= ~116 KB per CTA.
// ---------------------------------------------------------------------------

#define FEATC 128
#define CONTC 256
#define S2C   8192
#define S1C   73728        /* S2*9 */
#define S0C   663552       /* S1*9 */

// weight pool offsets (elements)
#define OFF_WP    0
#define OFF_W0    32768
#define OFF_WAGG0 65536
#define OFF_W1    81920
#define OFF_WAGG1 114688
#define W_TOTAL   131072

__device__ __half g_h0h[(long long)S0C * FEATC];   // 169.9 MB scratch
__device__ __half g_h1h[(long long)S1C * FEATC];   // 18.9 MB scratch
__device__ __half g_w16[W_TOTAL];                  // fp16 weights (all 5)

static __device__ __forceinline__ float leaky01(float x) {
    return x < 0.0f ? 0.1f * x : x;
}
static __device__ __forceinline__ uint32_t h2u(__half2 h) {
    return *reinterpret_cast<uint32_t*>(&h);
}

// mma.sync m16n8k16 row.col f32.f16.f16.f32, accumulate in place
static __device__ __forceinline__ void mma16816h(
    float* c, const uint32_t* a, const uint32_t* b)
{
    asm volatile(
        "mma.sync.aligned.m16n8k16.row.col.f32.f16.f16.f32 "
        "{%0,%1,%2,%3}, {%4,%5,%6,%7}, {%8,%9}, {%0,%1,%2,%3};"
        : "+f"(c[0]), "+f"(c[1]), "+f"(c[2]), "+f"(c[3])
        : "r"(a[0]), "r"(a[1]), "r"(a[2]), "r"(a[3]),
          "r"(b[0]), "r"(b[1]));
}

// ---------------------------------------------------------------------------
// k_prep: fp16 conversion of all weight matrices.
// ---------------------------------------------------------------------------
__global__ void k_prep(const float* __restrict__ Wp, const float* __restrict__ W0,
                       const float* __restrict__ Wagg0, const float* __restrict__ W1,
                       const float* __restrict__ Wagg1)
{
    int i = blockIdx.x * blockDim.x + threadIdx.x;
    if (i >= W_TOTAL) return;
    float v;
    if      (i < OFF_W0)    v = Wp[i - OFF_WP];
    else if (i < OFF_WAGG0) v = W0[i - OFF_W0];
    else if (i < OFF_W1)    v = Wagg0[i - OFF_WAGG0];
    else if (i < OFF_WAGG1) v = W1[i - OFF_W1];
    else                    v = Wagg1[i - OFF_WAGG1];
    g_w16[i] = __float2half_rn(v);
}

// ---------------------------------------------------------------------------
// k_h0_mma: fp16 GEMM, CTA 128x128.  Whole Wp resident in smem (pitch 264
// halfs -> conflict-free), ONE __syncthreads for the entire K=256 mainloop.
// 8 warps x (16 rows x 128 cols). Output fp16 to g_h0h.
// ---------------------------------------------------------------------------
#define WPITCH 264
#define H0_SMEM_BYTES (128 * WPITCH * 2)   /* 67,584 B */

__global__ __launch_bounds__(256, 2) void k_h0_mma(
    const float* __restrict__ content,   // [S0,256]
    const float* __restrict__ bp,        // [128]
    const float* __restrict__ node_emb,  // [N+1,128]
    const int*   __restrict__ parent)    // [S0]
{
    extern __shared__ __half Ws[];       // [128][WPITCH]

    const int tid  = threadIdx.x;
    const int lane = tid & 31;
    const int warp = tid >> 5;           // 0..7
    const int gID  = lane >> 2;          // 0..7
    const int qid  = lane & 3;           // 0..3
    const long long m0 = (long long)blockIdx.x * 128;
    const int mbase = warp * 16;

    // stage whole Wp: 128 rows x 256 halfs
#pragma unroll
    for (int it = 0; it < 16; it++) {
        int g = tid + 256 * it;          // 0..4095 uint4 groups
        int n = g >> 5;                  // 0..127
        int c = (g & 31) * 8;            // 0..248
        *(uint4*)&Ws[n * WPITCH + c] = *(const uint4*)(g_w16 + OFF_WP + n * CONTC + c);
    }

    float acc[16][4];
#pragma unroll
    for (int nj = 0; nj < 16; nj++)
#pragma unroll
        for (int t = 0; t < 4; t++) acc[nj][t] = 0.0f;

    __syncthreads();

#pragma unroll
    for (int kc = 0; kc < 4; kc++) {
#pragma unroll
        for (int s = 0; s < 4; s++) {
            uint32_t a[4];
            const float* abase = content + (m0 + mbase + gID) * (long long)CONTC
                               + kc * 64 + s * 16 + qid * 2;
#pragma unroll
            for (int rr = 0; rr < 2; rr++)
#pragma unroll
                for (int kk = 0; kk < 2; kk++) {
                    float2 v = *(const float2*)(abase + rr * 8 * CONTC + kk * 8);
                    a[rr + kk * 2] = h2u(__float22half2_rn(v));
                }
            int cb = kc * 64 + s * 16 + qid * 2;
#pragma unroll
            for (int nj = 0; nj < 16; nj++) {
                int n = nj * 8 + gID;
                uint32_t b[2];
                b[0] = *(const uint32_t*)&Ws[n * WPITCH + cb];
                b[1] = *(const uint32_t*)&Ws[n * WPITCH + cb + 8];
                mma16816h(acc[nj], a, b);
            }
        }
    }

    // epilogue: bias + leaky + node_emb gather -> g_h0h (fp16)
#pragma unroll
    for (int rr = 0; rr < 2; rr++) {
        long long r = m0 + mbase + rr * 8 + gID;
        long long p = (long long)parent[r] + 1;
        const float* ne = node_emb + p * FEATC;
        __half* orow = g_h0h + r * FEATC;
#pragma unroll
        for (int nj = 0; nj < 16; nj++) {
            int c = nj * 8 + qid * 2;
            float2 bv = *(const float2*)(bp + c);
            float2 nv = *(const float2*)(ne + c);
            float ox = leaky01(acc[nj][rr * 2 + 0] + bv.x) + nv.x;
            float oy = leaky01(acc[nj][rr * 2 + 1] + bv.y) + nv.y;
            *(__half2*)(orow + c) = __floats2half2_rn(ox, oy);
        }
    }
}

// ---------------------------------------------------------------------------
// k_conv_mma<LAYER>: 64 dst rows per CTA, all-fp16 single-term.
//  phase 1: Sagg fp16 in smem (gather-mean of 8 fp16 neighbors)
//  phase 2: kc=0,1: acc1 += X(g_h0h) @ W[:,0:128].T
//           kc=2,3: acc1 += Agg @ W[:,128:256].T ; acc2 += Agg @ Wagg.T
//  phase 3: epilogue (leaky + rownorm -> g_h1h for L0; fp32 sum -> dout L1)
// Dynamic smem (bytes), total 54,272:
//   [0, 17408)        Sagg  half[64][136]
//   [17408, +18432)   Bh    half[128][72]   (overlaid by red/scales in ep.)
//   [35840, +18432)   B2h   half[128][72]
// ---------------------------------------------------------------------------
#define CPITCH 136
#define BPAD   72
#define CONV_SMEM_BYTES (17408 + 2 * 18432)

template <int LAYER>
__global__ __launch_bounds__(256, 2) void k_conv_mma(
    const int*   __restrict__ nbr,   // random-edge srcs, nbr[8*dst + k]
    const float* __restrict__ b,     // [128]
    const float* __restrict__ bagg,  // [128]
    float*       __restrict__ dout)  // layer1 output
{
    extern __shared__ char smem[];
    __half* Sagg = (__half*)smem;                    // [64][CPITCH]
    __half* Bh   = (__half*)(smem + 17408);          // [128][BPAD]
    __half* B2h  = (__half*)(smem + 35840);          // [128][BPAD]
    float* red    = (float*)(smem + 17408);          // [64][2], epilogue only
    float* scales = (float*)(smem + 17408 + 512);    // [64]

    const int tid  = threadIdx.x;
    const int lane = tid & 31;
    const int warp = tid >> 5;
    const int wm   = warp & 3;           // 16-row m-block
    const int wn   = warp >> 2;          // 64-col n-block
    const int gID  = lane >> 2;
    const int qid  = lane & 3;
    const long long m0 = (long long)blockIdx.x * 64;
    const int mbase = wm * 16;
    const int nbase = wn * 64;
    const int WOFF  = (LAYER == 0) ? OFF_W0 : OFF_W1;
    const int AOFF  = (LAYER == 0) ? OFF_WAGG0 : OFF_WAGG1;
    const __half* hsrc = (LAYER == 0) ? g_h0h : g_h1h;

    // ---- phase 1: aggregate 8 neighbors (fp16 in, fp32 sum, fp16 out) ----
    for (int rr = warp; rr < 64; rr += 8) {
        long long drow = m0 + rr;
        const int4* e4 = (const int4*)(nbr + drow * 8);
        int4 e0 = e4[0], e1 = e4[1];
        int idx[8] = {e0.x, e0.y, e0.z, e0.w, e1.x, e1.y, e1.z, e1.w};
        float4 s = make_float4(0.f, 0.f, 0.f, 0.f);
#pragma unroll
        for (int k = 0; k < 8; k++) {
            long long si = idx[k];
            uint2 u = *(const uint2*)(hsrc + si * FEATC + lane * 4);
            float2 f0 = __half22float2(*(__half2*)&u.x);
            float2 f1 = __half22float2(*(__half2*)&u.y);
            s.x += f0.x; s.y += f0.y; s.z += f1.x; s.w += f1.y;
        }
        if (LAYER == 1) {
            uint2 u1 = *(const uint2*)(g_h1h + drow * FEATC + lane * 4);
            uint2 u0 = *(const uint2*)(g_h0h + drow * FEATC + lane * 4);
            float2 a0 = __half22float2(*(__half2*)&u1.x);
            float2 a1 = __half22float2(*(__half2*)&u1.y);
            float2 c0 = __half22float2(*(__half2*)&u0.x);
            float2 c1 = __half22float2(*(__half2*)&u0.y);
            s.x += a0.x - c0.x; s.y += a0.y - c0.y;
            s.z += a1.x - c1.x; s.w += a1.y - c1.y;
        }
        s.x *= 0.125f; s.y *= 0.125f; s.z *= 0.125f; s.w *= 0.125f;
        uint2 o;
        *(__half2*)&o.x = __floats2half2_rn(s.x, s.y);
        *(__half2*)&o.y = __floats2half2_rn(s.z, s.w);
        *(uint2*)&Sagg[rr * CPITCH + lane * 4] = o;
    }
    __syncthreads();

    // ---- phase 2: GEMMs, 4 K-chunks of 64, single-term fp16 ----
    float acc1[8][4], acc2[8][4];
#pragma unroll
    for (int nj = 0; nj < 8; nj++)
#pragma unroll
        for (int t = 0; t < 4; t++) { acc1[nj][t] = 0.f; acc2[nj][t] = 0.f; }

    for (int kc = 0; kc < 4; kc++) {
        const bool second = (kc >= 2);
        // stage W chunk: 128 rows x 64 cols
#pragma unroll
        for (int it = 0; it < 4; it++) {
            int g = tid + 256 * it;          // 0..1023 uint4 groups
            int n = g >> 3;                  // 0..127
            int c = (g & 7) * 8;             // 0..56
            *(uint4*)&Bh[n * BPAD + c] = *(const uint4*)(g_w16 + WOFF + n * CONTC + kc * 64 + c);
        }
        if (second) {
#pragma unroll
            for (int it = 0; it < 4; it++) {
                int g = tid + 256 * it;
                int n = g >> 3;
                int c = (g & 7) * 8;
                *(uint4*)&B2h[n * BPAD + c] =
                    *(const uint4*)(g_w16 + AOFF + n * FEATC + (kc - 2) * 64 + c);
            }
        }
        __syncthreads();

#pragma unroll
        for (int s = 0; s < 4; s++) {
            uint32_t a[4];
            if (!second) {
                const __half* ab = g_h0h + (m0 + mbase + gID) * (long long)FEATC
                                 + kc * 64 + s * 16 + qid * 2;
#pragma unroll
                for (int rr = 0; rr < 2; rr++)
#pragma unroll
                    for (int kk = 0; kk < 2; kk++)
                        a[rr + kk * 2] = *(const uint32_t*)(ab + rr * 8 * FEATC + kk * 8);
            } else {
                const __half* ab = Sagg + (mbase + gID) * CPITCH
                                 + (kc - 2) * 64 + s * 16 + qid * 2;
#pragma unroll
                for (int rr = 0; rr < 2; rr++)
#pragma unroll
                    for (int kk = 0; kk < 2; kk++)
                        a[rr + kk * 2] = *(const uint32_t*)(ab + rr * 8 * CPITCH + kk * 8);
            }
            int cb = s * 16 + qid * 2;
#pragma unroll
            for (int nj = 0; nj < 8; nj++) {
                int n = nbase + nj * 8 + gID;
                uint32_t bb[2];
                bb[0] = *(const uint32_t*)&Bh[n * BPAD + cb];
                bb[1] = *(const uint32_t*)&Bh[n * BPAD + cb + 8];
                mma16816h(acc1[nj], a, bb);
                if (second) {
                    uint32_t cc[2];
                    cc[0] = *(const uint32_t*)&B2h[n * BPAD + cb];
                    cc[1] = *(const uint32_t*)&B2h[n * BPAD + cb + 8];
                    mma16816h(acc2[nj], a, cc);
                }
            }
        }
        __syncthreads();
    }

    // ---- phase 3: epilogue ----
    float ss[2] = {0.f, 0.f};
#pragma unroll
    for (int rr = 0; rr < 2; rr++)
#pragma unroll
        for (int nj = 0; nj < 8; nj++) {
            int c = nbase + nj * 8 + qid * 2;
#pragma unroll
            for (int k = 0; k < 2; k++) {
                float t1 = acc1[nj][rr * 2 + k] + b[c + k];
                float t2 = acc2[nj][rr * 2 + k] + bagg[c + k];
                if (LAYER == 0) { t1 = leaky01(t1); t2 = leaky01(t2); }
                float v = t1 + t2;
                acc1[nj][rr * 2 + k] = v;
                if (LAYER == 0) ss[rr] = fmaf(v, v, ss[rr]);
            }
        }

    if (LAYER == 0) {
#pragma unroll
        for (int rr = 0; rr < 2; rr++) {
            float v = ss[rr];
            v += __shfl_xor_sync(0xFFFFFFFF, v, 1);
            v += __shfl_xor_sync(0xFFFFFFFF, v, 2);
            ss[rr] = v;
        }
        if (qid == 0) {
#pragma unroll
            for (int rr = 0; rr < 2; rr++) {
                int rl = mbase + rr * 8 + gID;
                red[rl * 2 + wn] = ss[rr];
            }
        }
        __syncthreads();
        if (tid < 64) {
            float s = red[tid * 2] + red[tid * 2 + 1];
            scales[tid] = 1.0f / fmaxf(sqrtf(s), 1e-6f);
        }
        __syncthreads();
#pragma unroll
        for (int rr = 0; rr < 2; rr++) {
            int rl = mbase + rr * 8 + gID;
            float sc = scales[rl];
            __half* orow = g_h1h + (m0 + rl) * (long long)FEATC;
#pragma unroll
            for (int nj = 0; nj < 8; nj++) {
                int c = nbase + nj * 8 + qid * 2;
                *(__half2*)(orow + c) = __floats2half2_rn(
                    acc1[nj][rr * 2 + 0] * sc, acc1[nj][rr * 2 + 1] * sc);
            }
        }
    } else {
#pragma unroll
        for (int rr = 0; rr < 2; rr++) {
            int rl = mbase + rr * 8 + gID;
            float* orow = dout + (m0 + rl) * (long long)FEATC;
#pragma unroll
            for (int nj = 0; nj < 8; nj++) {
                int c = nbase + nj * 8 + qid * 2;
                float2 o;
                o.x = acc1[nj][rr * 2 + 0];
                o.y = acc1[nj][rr * 2 + 1];
                *(float2*)(orow + c) = o;
            }
        }
    }
}

// ---------------------------------------------------------------------------
// kernel_launch
// ---------------------------------------------------------------------------
extern "C" void kernel_launch(void* const* d_in, const int* in_sizes, int n_in,
                              void* d_out, int out_size)
{
    const float* node_emb = (const float*)d_in[0];
    const float* content0 = (const float*)d_in[1];
    const float* Wp    = (const float*)d_in[2];
    const float* bp    = (const float*)d_in[3];
    const float* W0    = (const float*)d_in[4];
    const float* b0    = (const float*)d_in[5];
    const float* Wagg0 = (const float*)d_in[6];
    const float* bagg0 = (const float*)d_in[7];
    const float* W1    = (const float*)d_in[8];
    const float* b1    = (const float*)d_in[9];
    const float* Wagg1 = (const float*)d_in[10];
    const float* bagg1 = (const float*)d_in[11];
    const int* parent0 = (const int*)d_in[12];
    const int* src0    = (const int*)d_in[13];
    const int* src1    = (const int*)d_in[15];
    float* out = (float*)d_out;

    cudaFuncSetAttribute(k_h0_mma, cudaFuncAttributeMaxDynamicSharedMemorySize, H0_SMEM_BYTES);
    cudaFuncSetAttribute(k_conv_mma<0>, cudaFuncAttributeMaxDynamicSharedMemorySize, CONV_SMEM_BYTES);
    cudaFuncSetAttribute(k_conv_mma<1>, cudaFuncAttributeMaxDynamicSharedMemorySize, CONV_SMEM_BYTES);

    k_prep<<<(W_TOTAL + 255) / 256, 256>>>(Wp, W0, Wagg0, W1, Wagg1);
    k_h0_mma<<<S0C / 128, 256, H0_SMEM_BYTES>>>(content0, bp, node_emb, parent0);
    k_conv_mma<0><<<S1C / 64, 256, CONV_SMEM_BYTES>>>(src0 + S1C, b0, bagg0, nullptr);
    k_conv_mma<1><<<S2C / 64, 256, CONV_SMEM_BYTES>>>(src1 + S2C, b1, bagg1, out);
}

// round 11
// speedup vs baseline: 3.5250x; 1.0679x over previous
#include <cuda_runtime.h>
#include <cuda_fp16.h>
#include <cstdint>

// ---------------------------------------------------------------------------
// GraphSAGE with sampling, GB300 (compute_103 virtual arch -> no tcgen05).
// Round 11 (conv-only changes):
//  - conv: W fully smem-resident -> 4 syncs/CTA (was 8)
//  - conv: gather phase unrolled x2 (16 loads in flight, was 8)
//  - h0 / prep: unchanged from round 10 (h0 is near its DRAM floor)
// Env constraint: dynamic smem <= ~116 KB per CTA (conv uses 103,424 B).
// ---------------------------------------------------------------------------

#define FEATC 128
#define CONTC 256
#define S2C   8192
#define S1C   73728        /* S2*9 */
#define S0C   663552       /* S1*9 */

// weight pool offsets (elements)
#define OFF_WP    0
#define OFF_W0    32768
#define OFF_WAGG0 65536
#define OFF_W1    81920
#define OFF_WAGG1 114688
#define W_TOTAL   131072

__device__ __half g_h0h[(long long)S0C * FEATC];   // 169.9 MB scratch
__device__ __half g_h1h[(long long)S1C * FEATC];   // 18.9 MB scratch
__device__ __half g_w16[W_TOTAL];                  // fp16 weights (all 5)

static __device__ __forceinline__ float leaky01(float x) {
    return x < 0.0f ? 0.1f * x : x;
}
static __device__ __forceinline__ uint32_t h2u(__half2 h) {
    return *reinterpret_cast<uint32_t*>(&h);
}

// mma.sync m16n8k16 row.col f32.f16.f16.f32, accumulate in place
static __device__ __forceinline__ void mma16816h(
    float* c, const uint32_t* a, const uint32_t* b)
{
    asm volatile(
        "mma.sync.aligned.m16n8k16.row.col.f32.f16.f16.f32 "
        "{%0,%1,%2,%3}, {%4,%5,%6,%7}, {%8,%9}, {%0,%1,%2,%3};"
        : "+f"(c[0]), "+f"(c[1]), "+f"(c[2]), "+f"(c[3])
        : "r"(a[0]), "r"(a[1]), "r"(a[2]), "r"(a[3]),
          "r"(b[0]), "r"(b[1]));
}

// ---------------------------------------------------------------------------
// k_prep: fp16 conversion of all weight matrices.
// ---------------------------------------------------------------------------
__global__ void k_prep(const float* __restrict__ Wp, const float* __restrict__ W0,
                       const float* __restrict__ Wagg0, const float* __restrict__ W1,
                       const float* __restrict__ Wagg1)
{
    int i = blockIdx.x * blockDim.x + threadIdx.x;
    if (i >= W_TOTAL) return;
    float v;
    if      (i < OFF_W0)    v = Wp[i - OFF_WP];
    else if (i < OFF_WAGG0) v = W0[i - OFF_W0];
    else if (i < OFF_W1)    v = Wagg0[i - OFF_WAGG0];
    else if (i < OFF_WAGG1) v = W1[i - OFF_W1];
    else                    v = Wagg1[i - OFF_WAGG1];
    g_w16[i] = __float2half_rn(v);
}

// ---------------------------------------------------------------------------
// k_h0_mma: fp16 GEMM, CTA 128x128.  Whole Wp resident in smem, one sync.
// (unchanged from round 10)
// ---------------------------------------------------------------------------
#define WPITCH 264
#define H0_SMEM_BYTES (128 * WPITCH * 2)   /* 67,584 B */

__global__ __launch_bounds__(256, 2) void k_h0_mma(
    const float* __restrict__ content,   // [S0,256]
    const float* __restrict__ bp,        // [128]
    const float* __restrict__ node_emb,  // [N+1,128]
    const int*   __restrict__ parent)    // [S0]
{
    extern __shared__ __half Ws[];       // [128][WPITCH]

    const int tid  = threadIdx.x;
    const int lane = tid & 31;
    const int warp = tid >> 5;           // 0..7
    const int gID  = lane >> 2;          // 0..7
    const int qid  = lane & 3;           // 0..3
    const long long m0 = (long long)blockIdx.x * 128;
    const int mbase = warp * 16;

#pragma unroll
    for (int it = 0; it < 16; it++) {
        int g = tid + 256 * it;
        int n = g >> 5;
        int c = (g & 31) * 8;
        *(uint4*)&Ws[n * WPITCH + c] = *(const uint4*)(g_w16 + OFF_WP + n * CONTC + c);
    }

    float acc[16][4];
#pragma unroll
    for (int nj = 0; nj < 16; nj++)
#pragma unroll
        for (int t = 0; t < 4; t++) acc[nj][t] = 0.0f;

    __syncthreads();

#pragma unroll
    for (int kc = 0; kc < 4; kc++) {
#pragma unroll
        for (int s = 0; s < 4; s++) {
            uint32_t a[4];
            const float* abase = content + (m0 + mbase + gID) * (long long)CONTC
                               + kc * 64 + s * 16 + qid * 2;
#pragma unroll
            for (int rr = 0; rr < 2; rr++)
#pragma unroll
                for (int kk = 0; kk < 2; kk++) {
                    float2 v = *(const float2*)(abase + rr * 8 * CONTC + kk * 8);
                    a[rr + kk * 2] = h2u(__float22half2_rn(v));
                }
            int cb = kc * 64 + s * 16 + qid * 2;
#pragma unroll
            for (int nj = 0; nj < 16; nj++) {
                int n = nj * 8 + gID;
                uint32_t b[2];
                b[0] = *(const uint32_t*)&Ws[n * WPITCH + cb];
                b[1] = *(const uint32_t*)&Ws[n * WPITCH + cb + 8];
                mma16816h(acc[nj], a, b);
            }
        }
    }

#pragma unroll
    for (int rr = 0; rr < 2; rr++) {
        long long r = m0 + mbase + rr * 8 + gID;
        long long p = (long long)parent[r] + 1;
        const float* ne = node_emb + p * FEATC;
        __half* orow = g_h0h + r * FEATC;
#pragma unroll
        for (int nj = 0; nj < 16; nj++) {
            int c = nj * 8 + qid * 2;
            float2 bv = *(const float2*)(bp + c);
            float2 nv = *(const float2*)(ne + c);
            float ox = leaky01(acc[nj][rr * 2 + 0] + bv.x) + nv.x;
            float oy = leaky01(acc[nj][rr * 2 + 1] + bv.y) + nv.y;
            *(__half2*)(orow + c) = __floats2half2_rn(ox, oy);
        }
    }
}

// ---------------------------------------------------------------------------
// k_conv_mma<LAYER>: 64 dst rows per CTA, all-fp16 single-term.
// W fully smem-resident; Wagg staged in 2 chunks. 4 syncs per CTA.
// Dynamic smem (bytes), total 103,424:
//   [0, 17408)          Sagg  half[64][136]
//   [17408, +67584)     Wsm   half[128][264]  (whole W, K=256)
//   [84992, +18432)     B2    half[128][72]   (Wagg chunk; red/scales overlay)
// ---------------------------------------------------------------------------
#define CPITCH 136
#define BPAD   72
#define CONV_SMEM_BYTES (17408 + 67584 + 18432)

template <int LAYER>
__global__ __launch_bounds__(256, 2) void k_conv_mma(
    const int*   __restrict__ nbr,   // random-edge srcs, nbr[8*dst + k]
    const float* __restrict__ b,     // [128]
    const float* __restrict__ bagg,  // [128]
    float*       __restrict__ dout)  // layer1 output
{
    extern __shared__ char smem[];
    __half* Sagg = (__half*)smem;                    // [64][CPITCH]
    __half* Wsm  = (__half*)(smem + 17408);          // [128][WPITCH]
    __half* B2   = (__half*)(smem + 84992);          // [128][BPAD]
    float* red    = (float*)(smem + 84992);          // [64][2], epilogue only
    float* scales = (float*)(smem + 84992 + 512);    // [64]

    const int tid  = threadIdx.x;
    const int lane = tid & 31;
    const int warp = tid >> 5;
    const int wm   = warp & 3;           // 16-row m-block
    const int wn   = warp >> 2;          // 64-col n-block
    const int gID  = lane >> 2;
    const int qid  = lane & 3;
    const long long m0 = (long long)blockIdx.x * 64;
    const int mbase = wm * 16;
    const int nbase = wn * 64;
    const int WOFF  = (LAYER == 0) ? OFF_W0 : OFF_W1;
    const int AOFF  = (LAYER == 0) ? OFF_WAGG0 : OFF_WAGG1;
    const __half* hsrc = (LAYER == 0) ? g_h0h : g_h1h;

    // ---- stage whole W [128x256] and Wagg chunk0 [128x64] ----
#pragma unroll
    for (int it = 0; it < 16; it++) {
        int g = tid + 256 * it;
        int n = g >> 5;
        int c = (g & 31) * 8;
        *(uint4*)&Wsm[n * WPITCH + c] = *(const uint4*)(g_w16 + WOFF + n * CONTC + c);
    }
#pragma unroll
    for (int it = 0; it < 4; it++) {
        int g = tid + 256 * it;
        int n = g >> 3;
        int c = (g & 7) * 8;
        *(uint4*)&B2[n * BPAD + c] = *(const uint4*)(g_w16 + AOFF + n * FEATC + c);
    }

    // ---- phase 1: gather-mean, 2 rows in flight per warp iteration ----
#pragma unroll
    for (int rp = 0; rp < 4; rp++) {
        int rr0 = warp + rp * 16;
        int rr1 = rr0 + 8;
        long long d0 = m0 + rr0, d1 = m0 + rr1;
        int4 ea0 = *(const int4*)(nbr + d0 * 8);
        int4 eb0 = *(const int4*)(nbr + d0 * 8 + 4);
        int4 ea1 = *(const int4*)(nbr + d1 * 8);
        int4 eb1 = *(const int4*)(nbr + d1 * 8 + 4);
        int idx0[8] = {ea0.x, ea0.y, ea0.z, ea0.w, eb0.x, eb0.y, eb0.z, eb0.w};
        int idx1[8] = {ea1.x, ea1.y, ea1.z, ea1.w, eb1.x, eb1.y, eb1.z, eb1.w};
        uint2 u0[8], u1[8];
#pragma unroll
        for (int k = 0; k < 8; k++)
            u0[k] = *(const uint2*)(hsrc + (long long)idx0[k] * FEATC + lane * 4);
#pragma unroll
        for (int k = 0; k < 8; k++)
            u1[k] = *(const uint2*)(hsrc + (long long)idx1[k] * FEATC + lane * 4);

        float4 s0 = make_float4(0.f, 0.f, 0.f, 0.f);
        float4 s1 = make_float4(0.f, 0.f, 0.f, 0.f);
#pragma unroll
        for (int k = 0; k < 8; k++) {
            float2 f0 = __half22float2(*(__half2*)&u0[k].x);
            float2 f1 = __half22float2(*(__half2*)&u0[k].y);
            s0.x += f0.x; s0.y += f0.y; s0.z += f1.x; s0.w += f1.y;
            float2 g0 = __half22float2(*(__half2*)&u1[k].x);
            float2 g1 = __half22float2(*(__half2*)&u1[k].y);
            s1.x += g0.x; s1.y += g0.y; s1.z += g1.x; s1.w += g1.y;
        }
        if (LAYER == 1) {
            uint2 a1 = *(const uint2*)(g_h1h + d0 * FEATC + lane * 4);
            uint2 c1 = *(const uint2*)(g_h0h + d0 * FEATC + lane * 4);
            uint2 a2 = *(const uint2*)(g_h1h + d1 * FEATC + lane * 4);
            uint2 c2 = *(const uint2*)(g_h0h + d1 * FEATC + lane * 4);
            float2 p0 = __half22float2(*(__half2*)&a1.x), p1 = __half22float2(*(__half2*)&a1.y);
            float2 q0 = __half22float2(*(__half2*)&c1.x), q1 = __half22float2(*(__half2*)&c1.y);
            s0.x += p0.x - q0.x; s0.y += p0.y - q0.y;
            s0.z += p1.x - q1.x; s0.w += p1.y - q1.y;
            float2 r0 = __half22float2(*(__half2*)&a2.x), r1 = __half22float2(*(__half2*)&a2.y);
            float2 t0 = __half22float2(*(__half2*)&c2.x), t1 = __half22float2(*(__half2*)&c2.y);
            s1.x += r0.x - t0.x; s1.y += r0.y - t0.y;
            s1.z += r1.x - t1.x; s1.w += r1.y - t1.y;
        }
        s0.x *= 0.125f; s0.y *= 0.125f; s0.z *= 0.125f; s0.w *= 0.125f;
        s1.x *= 0.125f; s1.y *= 0.125f; s1.z *= 0.125f; s1.w *= 0.125f;
        uint2 o0, o1;
        *(__half2*)&o0.x = __floats2half2_rn(s0.x, s0.y);
        *(__half2*)&o0.y = __floats2half2_rn(s0.z, s0.w);
        *(__half2*)&o1.x = __floats2half2_rn(s1.x, s1.y);
        *(__half2*)&o1.y = __floats2half2_rn(s1.z, s1.w);
        *(uint2*)&Sagg[rr0 * CPITCH + lane * 4] = o0;
        *(uint2*)&Sagg[rr1 * CPITCH + lane * 4] = o1;
    }

    float acc1[8][4], acc2[8][4];
#pragma unroll
    for (int nj = 0; nj < 8; nj++)
#pragma unroll
        for (int t = 0; t < 4; t++) { acc1[nj][t] = 0.f; acc2[nj][t] = 0.f; }

    __syncthreads();   // sync 1: Sagg + Wsm + B2(chunk0) ready

    // ---- kc = 0,1: acc1 += X @ W[:,0:128].T  (no syncs) ----
#pragma unroll
    for (int kc = 0; kc < 2; kc++) {
#pragma unroll
        for (int s = 0; s < 4; s++) {
            uint32_t a[4];
            const __half* ab = g_h0h + (m0 + mbase + gID) * (long long)FEATC
                             + kc * 64 + s * 16 + qid * 2;
#pragma unroll
            for (int rr = 0; rr < 2; rr++)
#pragma unroll
                for (int kk = 0; kk < 2; kk++)
                    a[rr + kk * 2] = *(const uint32_t*)(ab + rr * 8 * FEATC + kk * 8);
            int cb = kc * 64 + s * 16 + qid * 2;
#pragma unroll
            for (int nj = 0; nj < 8; nj++) {
                int n = nbase + nj * 8 + gID;
                uint32_t bb[2];
                bb[0] = *(const uint32_t*)&Wsm[n * WPITCH + cb];
                bb[1] = *(const uint32_t*)&Wsm[n * WPITCH + cb + 8];
                mma16816h(acc1[nj], a, bb);
            }
        }
    }

    // ---- kc = 2: Agg @ (W[:,128:192] and Wagg[:,0:64])  (no sync before) ----
#pragma unroll
    for (int s = 0; s < 4; s++) {
        uint32_t a[4];
        const __half* ab = Sagg + (mbase + gID) * CPITCH + s * 16 + qid * 2;
#pragma unroll
        for (int rr = 0; rr < 2; rr++)
#pragma unroll
            for (int kk = 0; kk < 2; kk++)
                a[rr + kk * 2] = *(const uint32_t*)(ab + rr * 8 * CPITCH + kk * 8);
        int cb = 128 + s * 16 + qid * 2;
        int cb2 = s * 16 + qid * 2;
#pragma unroll
        for (int nj = 0; nj < 8; nj++) {
            int n = nbase + nj * 8 + gID;
            uint32_t bb[2], cc[2];
            bb[0] = *(const uint32_t*)&Wsm[n * WPITCH + cb];
            bb[1] = *(const uint32_t*)&Wsm[n * WPITCH + cb + 8];
            cc[0] = *(const uint32_t*)&B2[n * BPAD + cb2];
            cc[1] = *(const uint32_t*)&B2[n * BPAD + cb2 + 8];
            mma16816h(acc1[nj], a, bb);
            mma16816h(acc2[nj], a, cc);
        }
    }

    __syncthreads();   // sync 2: B2 chunk0 consumed
    // stage Wagg chunk1 [128 x 64] (cols 64..127)
#pragma unroll
    for (int it = 0; it < 4; it++) {
        int g = tid + 256 * it;
        int n = g >> 3;
        int c = (g & 7) * 8;
        *(uint4*)&B2[n * BPAD + c] = *(const uint4*)(g_w16 + AOFF + n * FEATC + 64 + c);
    }
    __syncthreads();   // sync 3: B2 chunk1 ready

    // ---- kc = 3: Agg @ (W[:,192:256] and Wagg[:,64:128]) ----
#pragma unroll
    for (int s = 0; s < 4; s++) {
        uint32_t a[4];
        const __half* ab = Sagg + (mbase + gID) * CPITCH + 64 + s * 16 + qid * 2;
#pragma unroll
        for (int rr = 0; rr < 2; rr++)
#pragma unroll
            for (int kk = 0; kk < 2; kk++)
                a[rr + kk * 2] = *(const uint32_t*)(ab + rr * 8 * CPITCH + kk * 8);
        int cb = 192 + s * 16 + qid * 2;
        int cb2 = s * 16 + qid * 2;
#pragma unroll
        for (int nj = 0; nj < 8; nj++) {
            int n = nbase + nj * 8 + gID;
            uint32_t bb[2], cc[2];
            bb[0] = *(const uint32_t*)&Wsm[n * WPITCH + cb];
            bb[1] = *(const uint32_t*)&Wsm[n * WPITCH + cb + 8];
            cc[0] = *(const uint32_t*)&B2[n * BPAD + cb2];
            cc[1] = *(const uint32_t*)&B2[n * BPAD + cb2 + 8];
            mma16816h(acc1[nj], a, bb);
            mma16816h(acc2[nj], a, cc);
        }
    }
    __syncthreads();   // sync 4: B2 region free for red/scales overlay

    // ---- epilogue ----
    float ss[2] = {0.f, 0.f};
#pragma unroll
    for (int rr = 0; rr < 2; rr++)
#pragma unroll
        for (int nj = 0; nj < 8; nj++) {
            int c = nbase + nj * 8 + qid * 2;
#pragma unroll
            for (int k = 0; k < 2; k++) {
                float t1 = acc1[nj][rr * 2 + k] + b[c + k];
                float t2 = acc2[nj][rr * 2 + k] + bagg[c + k];
                if (LAYER == 0) { t1 = leaky01(t1); t2 = leaky01(t2); }
                float v = t1 + t2;
                acc1[nj][rr * 2 + k] = v;
                if (LAYER == 0) ss[rr] = fmaf(v, v, ss[rr]);
            }
        }

    if (LAYER == 0) {
#pragma unroll
        for (int rr = 0; rr < 2; rr++) {
            float v = ss[rr];
            v += __shfl_xor_sync(0xFFFFFFFF, v, 1);
            v += __shfl_xor_sync(0xFFFFFFFF, v, 2);
            ss[rr] = v;
        }
        if (qid == 0) {
#pragma unroll
            for (int rr = 0; rr < 2; rr++) {
                int rl = mbase + rr * 8 + gID;
                red[rl * 2 + wn] = ss[rr];
            }
        }
        __syncthreads();
        if (tid < 64) {
            float s = red[tid * 2] + red[tid * 2 + 1];
            scales[tid] = 1.0f / fmaxf(sqrtf(s), 1e-6f);
        }
        __syncthreads();
#pragma unroll
        for (int rr = 0; rr < 2; rr++) {
            int rl = mbase + rr * 8 + gID;
            float sc = scales[rl];
            __half* orow = g_h1h + (m0 + rl) * (long long)FEATC;
#pragma unroll
            for (int nj = 0; nj < 8; nj++) {
                int c = nbase + nj * 8 + qid * 2;
                *(__half2*)(orow + c) = __floats2half2_rn(
                    acc1[nj][rr * 2 + 0] * sc, acc1[nj][rr * 2 + 1] * sc);
            }
        }
    } else {
#pragma unroll
        for (int rr = 0; rr < 2; rr++) {
            int rl = mbase + rr * 8 + gID;
            float* orow = dout + (m0 + rl) * (long long)FEATC;
#pragma unroll
            for (int nj = 0; nj < 8; nj++) {
                int c = nbase + nj * 8 + qid * 2;
                float2 o;
                o.x = acc1[nj][rr * 2 + 0];
                o.y = acc1[nj][rr * 2 + 1];
                *(float2*)(orow + c) = o;
            }
        }
    }
}

// ---------------------------------------------------------------------------
// kernel_launch
// ---------------------------------------------------------------------------
extern "C" void kernel_launch(void* const* d_in, const int* in_sizes, int n_in,
                              void* d_out, int out_size)
{
    const float* node_emb = (const float*)d_in[0];
    const float* content0 = (const float*)d_in[1];
    const float* Wp    = (const float*)d_in[2];
    const float* bp    = (const float*)d_in[3];
    const float* W0    = (const float*)d_in[4];
    const float* b0    = (const float*)d_in[5];
    const float* Wagg0 = (const float*)d_in[6];
    const float* bagg0 = (const float*)d_in[7];
    const float* W1    = (const float*)d_in[8];
    const float* b1    = (const float*)d_in[9];
    const float* Wagg1 = (const float*)d_in[10];
    const float* bagg1 = (const float*)d_in[11];
    const int* parent0 = (const int*)d_in[12];
    const int* src0    = (const int*)d_in[13];
    const int* src1    = (const int*)d_in[15];
    float* out = (float*)d_out;

    cudaFuncSetAttribute(k_h0_mma, cudaFuncAttributeMaxDynamicSharedMemorySize, H0_SMEM_BYTES);
    cudaFuncSetAttribute(k_conv_mma<0>, cudaFuncAttributeMaxDynamicSharedMemorySize, CONV_SMEM_BYTES);
    cudaFuncSetAttribute(k_conv_mma<1>, cudaFuncAttributeMaxDynamicSharedMemorySize, CONV_SMEM_BYTES);

    k_prep<<<(W_TOTAL + 255) / 256, 256>>>(Wp, W0, Wagg0, W1, Wagg1);
    k_h0_mma<<<S0C / 128, 256, H0_SMEM_BYTES>>>(content0, bp, node_emb, parent0);
    k_conv_mma<0><<<S1C / 64, 256, CONV_SMEM_BYTES>>>(src0 + S1C, b0, bagg0, nullptr);
    k_conv_mma<1><<<S2C / 64, 256, CONV_SMEM_BYTES>>>(src1 + S2C, b1, bagg1, out);
}